// round 1
// baseline (speedup 1.0000x reference)
#include <cuda_runtime.h>
#include <math.h>

// ---------------------------------------------------------------------------
// Problem constants (match reference)
// ---------------------------------------------------------------------------
namespace {
constexpr int BATCH = 128, NNODE = 512, INC = 128, HID = 32, KA = 100, KB = 10, OC = 10;
constexpr int TOT = BATCH * NNODE;          // 65536
constexpr float EPSV = 1e-15f;

// scratch arena offsets (floats)
constexpr size_t SZ_ADJ   = (size_t)BATCH * NNODE * NNODE;       // 33,554,432
constexpr size_t OFF_ADJ  = 0;
constexpr size_t OFF_DEG  = OFF_ADJ + SZ_ADJ;                    // in-deg (no self loop)
constexpr size_t OFF_DFLAT= OFF_DEG + TOT;                       // out-deg row sums
constexpr size_t OFF_LOSSB= OFF_DFLAT + TOT;                     // per-graph loss
constexpr size_t ZERO_CNT = OFF_LOSSB + BATCH;                   // contiguous zero range
constexpr size_t OFF_XWP  = ZERO_CNT;                            // dis*x@W
constexpr size_t OFF_AGG  = OFF_XWP  + (size_t)TOT * HID;
constexpr size_t OFF_H    = OFF_AGG  + (size_t)TOT * HID;
constexpr size_t OFF_S1   = OFF_H    + (size_t)TOT * HID;
constexpr size_t OFF_T1   = OFF_S1   + (size_t)TOT * KA;
constexpr size_t OFF_ADJR1= OFF_T1   + (size_t)TOT * KA;
constexpr size_t OFF_SS1  = OFF_ADJR1+ (size_t)BATCH * KA * KA;
constexpr size_t OFF_X1   = OFF_SS1  + (size_t)BATCH * KA * KA;
constexpr size_t OFF_ADJ1 = OFF_X1   + (size_t)BATCH * KA * HID;
constexpr size_t OFF_DFLAT2=OFF_ADJ1 + (size_t)BATCH * KA * KA;
constexpr size_t OFF_T2   = OFF_DFLAT2+(size_t)BATCH * KA;
constexpr size_t OFF_X2   = OFF_T2   + (size_t)BATCH * KA * HID;
constexpr size_t OFF_S2   = OFF_X2   + (size_t)BATCH * KA * HID;
constexpr size_t OFF_TT2  = OFF_S2   + (size_t)BATCH * KA * KB;
constexpr size_t OFF_ADJR2= OFF_TT2  + (size_t)BATCH * KA * KB;
constexpr size_t OFF_SS2  = OFF_ADJR2+ (size_t)BATCH * KB * KB;
constexpr size_t OFF_X3   = OFF_SS2  + (size_t)BATCH * KB * KB;
constexpr size_t OFF_ADJ2 = OFF_X3   + (size_t)BATCH * KB * HID;
constexpr size_t OFF_T3   = OFF_ADJ2 + (size_t)BATCH * KB * KB;
constexpr size_t OFF_X4   = OFF_T3   + (size_t)BATCH * KB * HID;
constexpr size_t SCRATCH_TOTAL = OFF_X4 + (size_t)BATCH * KB * HID;
}  // namespace

__device__ __align__(16) float g_scratch[SCRATCH_TOTAL];

// ---------------------------------------------------------------------------
// zero the adjacency + degree + loss range
// ---------------------------------------------------------------------------
__global__ void zero_kernel(float4* p, size_t n4) {
    size_t i = (size_t)blockIdx.x * blockDim.x + threadIdx.x;
    size_t st = (size_t)gridDim.x * blockDim.x;
    float4 z = make_float4(0.f, 0.f, 0.f, 0.f);
    for (; i < n4; i += st) p[i] = z;
}

// ---------------------------------------------------------------------------
// scatter edges: dense adjacency + in-degree (gcn) + out-degree row sums
// ---------------------------------------------------------------------------
__global__ void scatter_kernel(const int* __restrict__ ei, int E,
                               float* __restrict__ adj,
                               float* __restrict__ deg,
                               float* __restrict__ dflat) {
    int e = blockIdx.x * blockDim.x + threadIdx.x;
    if (e >= E) return;
    int s = ei[e];
    int d = ei[E + e];
    int b  = s >> 9;           // / NNODE
    int sl = s & 511;
    int dl = d & 511;
    atomicAdd(&adj[((size_t)b << 18) + ((size_t)sl << 9) + dl], 1.0f);
    atomicAdd(&deg[d], 1.0f);
    atomicAdd(&dflat[s], 1.0f);
}

// ---------------------------------------------------------------------------
// xwp[g][c] = rsqrt(deg[g]+1) * sum_k x[g][k] * W[k][c]
// ---------------------------------------------------------------------------
__global__ __launch_bounds__(256) void xwp_kernel(const float* __restrict__ x,
                                                  const float* __restrict__ W,
                                                  const float* __restrict__ deg,
                                                  float* __restrict__ xwp) {
    __shared__ float Ws[INC * HID];   // 16 KB
    __shared__ float xs[8][INC];      // 4 KB
    int tid = threadIdx.y * 32 + threadIdx.x;
    for (int t = tid; t < INC * HID; t += 256) Ws[t] = W[t];
    int r0 = blockIdx.x * 8;
    for (int t = tid; t < 8 * INC; t += 256) {
        int r = t >> 7, k = t & 127;
        xs[r][k] = x[(size_t)(r0 + r) * INC + k];
    }
    __syncthreads();
    int c = threadIdx.x, r = threadIdx.y;
    float acc = 0.f;
#pragma unroll 8
    for (int k = 0; k < INC; k++) acc += xs[r][k] * Ws[k * HID + c];
    int g = r0 + r;
    float dis = rsqrtf(deg[g] + 1.0f);
    xwp[(size_t)g * HID + c] = dis * acc;
}

// ---------------------------------------------------------------------------
// Generic batched GEMMs. 64x64 tile, 16-deep K step, 4x4 micro-tile.
//   atb: C[b][i][j] = sum_n A[b][n][i] * B[b][n][j]   (A^T B)
//   ab : C[b][i][j] = sum_m A[b][i][m] * B[b][m][j]   (A B)
// ---------------------------------------------------------------------------
__global__ __launch_bounds__(256) void atb_kernel(const float* __restrict__ A,
                                                  const float* __restrict__ Bm,
                                                  float* __restrict__ C,
                                                  int n, int I, int J) {
    int b = blockIdx.z;
    A  += (size_t)b * n * I;
    Bm += (size_t)b * n * J;
    C  += (size_t)b * I * J;
    __shared__ float As[16][64];
    __shared__ float Bs[16][64];
    int i0 = blockIdx.y * 64, j0 = blockIdx.x * 64;
    int tid = threadIdx.x;
    int tx = tid & 15, ty = tid >> 4;
    float acc[4][4] = {};
    for (int n0 = 0; n0 < n; n0 += 16) {
        for (int t = tid; t < 16 * 64; t += 256) {
            int kk = t >> 6, ii = t & 63;
            int nn = n0 + kk;
            As[kk][ii] = (nn < n && i0 + ii < I) ? A[(size_t)nn * I + i0 + ii] : 0.f;
            Bs[kk][ii] = (nn < n && j0 + ii < J) ? Bm[(size_t)nn * J + j0 + ii] : 0.f;
        }
        __syncthreads();
#pragma unroll
        for (int kk = 0; kk < 16; kk++) {
            float a[4], bb[4];
#pragma unroll
            for (int u = 0; u < 4; u++) { a[u] = As[kk][ty * 4 + u]; bb[u] = Bs[kk][tx * 4 + u]; }
#pragma unroll
            for (int u = 0; u < 4; u++)
#pragma unroll
                for (int v = 0; v < 4; v++) acc[u][v] += a[u] * bb[v];
        }
        __syncthreads();
    }
#pragma unroll
    for (int u = 0; u < 4; u++) {
        int i = i0 + ty * 4 + u;
        if (i >= I) continue;
#pragma unroll
        for (int v = 0; v < 4; v++) {
            int j = j0 + tx * 4 + v;
            if (j < J) C[(size_t)i * J + j] = acc[u][v];
        }
    }
}

__global__ __launch_bounds__(256) void ab_kernel(const float* __restrict__ A,
                                                 const float* __restrict__ Bm,
                                                 float* __restrict__ C,
                                                 int I, int M, int J) {
    int b = blockIdx.z;
    A  += (size_t)b * I * M;
    Bm += (size_t)b * M * J;
    C  += (size_t)b * I * J;
    __shared__ float As[16][64];
    __shared__ float Bs[16][64];
    int i0 = blockIdx.y * 64, j0 = blockIdx.x * 64;
    int tid = threadIdx.x;
    int tx = tid & 15, ty = tid >> 4;
    float acc[4][4] = {};
    for (int m0 = 0; m0 < M; m0 += 16) {
        for (int t = tid; t < 16 * 64; t += 256) {
            // As: kk fast within thread index for coalesced 16-float row chunks
            int kk = t & 15, ii = t >> 4;
            As[kk][ii] = (m0 + kk < M && i0 + ii < I) ? A[(size_t)(i0 + ii) * M + m0 + kk] : 0.f;
            int kk2 = t >> 6, jj = t & 63;
            Bs[kk2][jj] = (m0 + kk2 < M && j0 + jj < J) ? Bm[(size_t)(m0 + kk2) * J + j0 + jj] : 0.f;
        }
        __syncthreads();
#pragma unroll
        for (int kk = 0; kk < 16; kk++) {
            float a[4], bb[4];
#pragma unroll
            for (int u = 0; u < 4; u++) { a[u] = As[kk][ty * 4 + u]; bb[u] = Bs[kk][tx * 4 + u]; }
#pragma unroll
            for (int u = 0; u < 4; u++)
#pragma unroll
                for (int v = 0; v < 4; v++) acc[u][v] += a[u] * bb[v];
        }
        __syncthreads();
    }
#pragma unroll
    for (int u = 0; u < 4; u++) {
        int i = i0 + ty * 4 + u;
        if (i >= I) continue;
#pragma unroll
        for (int v = 0; v < 4; v++) {
            int j = j0 + tx * 4 + v;
            if (j < J) C[(size_t)i * J + j] = acc[u][v];
        }
    }
}

// ---------------------------------------------------------------------------
// GCN epilogue: h = relu( dis_d * (agg + xwp) + b )
// ---------------------------------------------------------------------------
__global__ void ep1_kernel(const float* __restrict__ agg,
                           const float* __restrict__ xwp,
                           const float* __restrict__ deg,
                           const float* __restrict__ bias,
                           float* __restrict__ h) {
    int idx = blockIdx.x * blockDim.x + threadIdx.x;
    if (idx >= TOT * HID) return;
    int g = idx >> 5, c = idx & 31;
    float dis = rsqrtf(deg[g] + 1.0f);
    float v = dis * (agg[idx] + xwp[idx]) + bias[c];
    h[idx] = fmaxf(v, 0.f);
}

// ---------------------------------------------------------------------------
// pooled assignment: S = softmax(X @ W + b, axis=-1)   one warp per row, HID=32
// ---------------------------------------------------------------------------
__global__ void pool_softmax(const float* __restrict__ X, const float* __restrict__ W,
                             const float* __restrict__ bias, float* __restrict__ Sout,
                             int rows, int K) {
    int gw = (blockIdx.x * blockDim.x + threadIdx.x) >> 5;
    int lane = threadIdx.x & 31;
    if (gw >= rows) return;
    float xv = X[(size_t)gw * HID + lane];
    int slots = (K + 31) >> 5;       // <= 4
    float vals[4];
    float mx = -INFINITY;
    for (int t = 0; t < slots; t++) {
        int k = t * 32 + lane;
        float acc = 0.f;
#pragma unroll
        for (int c = 0; c < HID; c++) {
            float w = (k < K) ? W[c * K + k] : 0.f;
            acc += __shfl_sync(0xffffffffu, xv, c) * w;
        }
        float v = (k < K) ? acc + bias[k] : -INFINITY;
        vals[t] = v;
        mx = fmaxf(mx, v);
    }
#pragma unroll
    for (int o = 16; o; o >>= 1) mx = fmaxf(mx, __shfl_xor_sync(0xffffffffu, mx, o));
    float sum = 0.f;
    for (int t = 0; t < slots; t++) {
        int k = t * 32 + lane;
        float e = (k < K) ? expf(vals[t] - mx) : 0.f;
        vals[t] = e;
        sum += e;
    }
#pragma unroll
    for (int o = 16; o; o >>= 1) sum += __shfl_xor_sync(0xffffffffu, sum, o);
    float inv = 1.0f / sum;
    for (int t = 0; t < slots; t++) {
        int k = t * 32 + lane;
        if (k < K) Sout[(size_t)gw * K + k] = vals[t] * inv;
    }
}

// ---------------------------------------------------------------------------
// per-graph mincut losses + adjacency normalization
// ---------------------------------------------------------------------------
__device__ __forceinline__ float blockReduce128(float v, float* sm) {
    int t = threadIdx.x;
    sm[t] = v;
    __syncthreads();
    for (int s = 64; s > 0; s >>= 1) {
        if (t < s) sm[t] += sm[t + s];
        __syncthreads();
    }
    float r = sm[0];
    __syncthreads();
    return r;
}

__global__ void loss_norm_kernel(const float* __restrict__ raw,
                                 const float* __restrict__ ss,
                                 const float* __restrict__ s,
                                 const float* __restrict__ dflat,
                                 float* __restrict__ adjn,
                                 float* __restrict__ lossb,
                                 int k, int n) {
    int b = blockIdx.x;
    raw  += (size_t)b * k * k;
    ss   += (size_t)b * k * k;
    s    += (size_t)b * n * k;
    dflat+= (size_t)b * n;
    adjn += (size_t)b * k * k;
    __shared__ float sm[128];
    __shared__ float dc[128];
    int tid = threadIdx.x;

    // trace(raw)
    float v = 0.f;
    for (int i = tid; i < k; i += 128) v += raw[i * k + i];
    float num = blockReduce128(v, sm);

    // den = sum s^2 * dflat
    v = 0.f;
    for (int idx = tid; idx < n * k; idx += 128) {
        int nn = idx / k;
        float sv = s[idx];
        v += sv * sv * dflat[nn];
    }
    float den = blockReduce128(v, sm);

    // frobenius norm of ss
    v = 0.f;
    for (int idx = tid; idx < k * k; idx += 128) { float t = ss[idx]; v += t * t; }
    float nrm = sqrtf(blockReduce128(v, sm));

    // ortho = || ss/nrm - I/sqrt(k) ||_F
    float invn = 1.0f / nrm;
    float dk = rsqrtf((float)k);
    v = 0.f;
    for (int idx = tid; idx < k * k; idx += 128) {
        int i = idx / k, j = idx - i * k;
        float t = ss[idx] * invn - ((i == j) ? dk : 0.f);
        v += t * t;
    }
    float ortho = sqrtf(blockReduce128(v, sm));

    // row sums of zero-diag raw; normalize
    for (int i = tid; i < k; i += 128) {
        float r = 0.f;
        for (int j = 0; j < k; j++) if (j != i) r += raw[i * k + j];
        dc[i] = sqrtf(r) + EPSV;
    }
    __syncthreads();
    for (int idx = tid; idx < k * k; idx += 128) {
        int i = idx / k, j = idx - i * k;
        adjn[idx] = (i == j) ? 0.f : raw[idx] / (dc[i] * dc[j]);
    }
    if (tid == 0) lossb[b] += -num / den + ortho;
}

// ---------------------------------------------------------------------------
// dflat2 = adj1.sum(-1)
// ---------------------------------------------------------------------------
__global__ void rowsum_kernel(const float* __restrict__ A, float* __restrict__ out,
                              int rows, int len) {
    int idx = blockIdx.x * blockDim.x + threadIdx.x;
    if (idx >= rows) return;
    const float* r = A + (size_t)idx * len;
    float v = 0.f;
    for (int j = 0; j < len; j++) v += r[j];
    out[idx] = v;
}

// ---------------------------------------------------------------------------
// dense graph conv epilogue: out = act( t @ relW + relb + x @ rootW )
// one warp per row (HID = 32)
// ---------------------------------------------------------------------------
__global__ void conv_ep(const float* __restrict__ t, const float* __restrict__ xin,
                        const float* __restrict__ relW, const float* __restrict__ relb,
                        const float* __restrict__ rootW, float* __restrict__ out,
                        int rows, int do_relu) {
    int w = (blockIdx.x * blockDim.x + threadIdx.x) >> 5;
    int lane = threadIdx.x & 31;
    if (w >= rows) return;
    float tv = t[(size_t)w * HID + lane];
    float xv = xin[(size_t)w * HID + lane];
    float acc = relb[lane];
#pragma unroll
    for (int kk = 0; kk < HID; kk++) {
        acc += __shfl_sync(0xffffffffu, tv, kk) * relW[kk * HID + lane]
             + __shfl_sync(0xffffffffu, xv, kk) * rootW[kk * HID + lane];
    }
    if (do_relu) acc = fmaxf(acc, 0.f);
    out[(size_t)w * HID + lane] = acc;
}

// ---------------------------------------------------------------------------
// head: mean over nodes -> lin1 relu -> lin2 -> log_softmax -> d_out
// one 32-thread block per graph
// ---------------------------------------------------------------------------
__global__ void head_kernel(const float* __restrict__ x4,
                            const float* __restrict__ l1W, const float* __restrict__ l1b,
                            const float* __restrict__ l2W, const float* __restrict__ l2b,
                            float* __restrict__ out) {
    int b = blockIdx.x, lane = threadIdx.x;
    const float* xb = x4 + (size_t)b * KB * HID;
    float g = 0.f;
#pragma unroll
    for (int r = 0; r < KB; r++) g += xb[r * HID + lane];
    g *= (1.0f / KB);
    float acc = l1b[lane];
#pragma unroll
    for (int kk = 0; kk < HID; kk++) acc += __shfl_sync(0xffffffffu, g, kk) * l1W[kk * HID + lane];
    float gg = fmaxf(acc, 0.f);
    float acc2 = (lane < OC) ? l2b[lane] : 0.f;
#pragma unroll
    for (int kk = 0; kk < HID; kk++) {
        float w = (lane < OC) ? l2W[kk * OC + lane] : 0.f;
        acc2 += __shfl_sync(0xffffffffu, gg, kk) * w;
    }
    float val = (lane < OC) ? acc2 : -INFINITY;
    float m = val;
#pragma unroll
    for (int o = 16; o; o >>= 1) m = fmaxf(m, __shfl_xor_sync(0xffffffffu, m, o));
    float e = (lane < OC) ? expf(val - m) : 0.f;
    float ssum = e;
#pragma unroll
    for (int o = 16; o; o >>= 1) ssum += __shfl_xor_sync(0xffffffffu, ssum, o);
    if (lane < OC) out[b * OC + lane] = val - m - logf(ssum);
}

// ---------------------------------------------------------------------------
// final: total loss = mean over graphs of (mc1+o1+mc2+o2)
// ---------------------------------------------------------------------------
__global__ void final_kernel(const float* __restrict__ lossb, float* __restrict__ out,
                             int out_size) {
    __shared__ float sm[128];
    int t = threadIdx.x;
    sm[t] = lossb[t];
    __syncthreads();
    for (int s = 64; s > 0; s >>= 1) {
        if (t < s) sm[t] += sm[t + s];
        __syncthreads();
    }
    if (t == 0 && out_size > BATCH * OC) out[BATCH * OC] = sm[0] / (float)BATCH;
}

// ---------------------------------------------------------------------------
// launch
// ---------------------------------------------------------------------------
extern "C" void kernel_launch(void* const* d_in, const int* in_sizes, int n_in,
                              void* d_out, int out_size) {
    const float* x    = (const float*)d_in[0];
    const int*   ei   = (const int*)  d_in[1];
    const float* c1W  = (const float*)d_in[3];
    const float* c1b  = (const float*)d_in[4];
    const float* p1W  = (const float*)d_in[5];
    const float* p1b  = (const float*)d_in[6];
    const float* c2rW = (const float*)d_in[7];
    const float* c2rb = (const float*)d_in[8];
    const float* c2oW = (const float*)d_in[9];
    const float* p2W  = (const float*)d_in[10];
    const float* p2b  = (const float*)d_in[11];
    const float* c3rW = (const float*)d_in[12];
    const float* c3rb = (const float*)d_in[13];
    const float* c3oW = (const float*)d_in[14];
    const float* l1W  = (const float*)d_in[15];
    const float* l1b  = (const float*)d_in[16];
    const float* l2W  = (const float*)d_in[17];
    const float* l2b  = (const float*)d_in[18];
    float* out = (float*)d_out;
    int E = in_sizes[1] / 2;

    void* sp = nullptr;
    cudaGetSymbolAddress(&sp, g_scratch);
    float* S = (float*)sp;
    float* adj = S + OFF_ADJ;

    // 0) zero adjacency + degrees + per-graph loss
    zero_kernel<<<4096, 256>>>((float4*)S, ZERO_CNT / 4);
    // 1) build dense adjacency + degrees
    scatter_kernel<<<(E + 255) / 256, 256>>>(ei, E, adj, S + OFF_DEG, S + OFF_DFLAT);
    // 2) xwp = dis * x @ conv1_W
    xwp_kernel<<<TOT / 8, dim3(32, 8)>>>(x, c1W, S + OFF_DEG, S + OFF_XWP);
    // 3) agg = A^T xwp (per graph)
    { dim3 g(1, NNODE / 64, BATCH); atb_kernel<<<g, 256>>>(adj, S + OFF_XWP, S + OFF_AGG, NNODE, NNODE, HID); }
    // 4) h = relu(dis*(agg+xwp)+b)
    ep1_kernel<<<TOT * HID / 256, 256>>>(S + OFF_AGG, S + OFF_XWP, S + OFF_DEG, c1b, S + OFF_H);
    // 5) s1 = softmax(h @ p1W + b)
    pool_softmax<<<TOT * 32 / 256, 256>>>(S + OFF_H, p1W, p1b, S + OFF_S1, TOT, KA);
    // 6) T1 = A @ s1  (dominant GEMM)
    { dim3 g((KA + 63) / 64, NNODE / 64, BATCH); ab_kernel<<<g, 256>>>(adj, S + OFF_S1, S + OFF_T1, NNODE, NNODE, KA); }
    // 7) raw_adj1 = s1^T T1 ; ss1 = s1^T s1 ; x1 = s1^T h
    { dim3 g(2, 2, BATCH); atb_kernel<<<g, 256>>>(S + OFF_S1, S + OFF_T1, S + OFF_ADJR1, NNODE, KA, KA); }
    { dim3 g(2, 2, BATCH); atb_kernel<<<g, 256>>>(S + OFF_S1, S + OFF_S1, S + OFF_SS1, NNODE, KA, KA); }
    { dim3 g(1, 2, BATCH); atb_kernel<<<g, 256>>>(S + OFF_S1, S + OFF_H, S + OFF_X1, NNODE, KA, HID); }
    // 8) losses + adj1
    loss_norm_kernel<<<BATCH, 128>>>(S + OFF_ADJR1, S + OFF_SS1, S + OFF_S1, S + OFF_DFLAT,
                                     S + OFF_ADJ1, S + OFF_LOSSB, KA, NNODE);
    // 9) dflat2 = adj1.sum(-1)
    rowsum_kernel<<<(BATCH * KA + 255) / 256, 256>>>(S + OFF_ADJ1, S + OFF_DFLAT2, BATCH * KA, KA);
    // 10) conv2: t2 = adj1 @ x1 ; x2 = relu(t2@relW + b + x1@rootW)
    { dim3 g(1, (KA + 63) / 64, BATCH); ab_kernel<<<g, 256>>>(S + OFF_ADJ1, S + OFF_X1, S + OFF_T2, KA, KA, HID); }
    conv_ep<<<BATCH * KA * 32 / 256, 256>>>(S + OFF_T2, S + OFF_X1, c2rW, c2rb, c2oW, S + OFF_X2, BATCH * KA, 1);
    // 11) s2 = softmax(x2 @ p2W + b)
    pool_softmax<<<BATCH * KA * 32 / 256, 256>>>(S + OFF_X2, p2W, p2b, S + OFF_S2, BATCH * KA, KB);
    // 12) T2 = adj1 @ s2 ; raw_adj2 = s2^T T2 ; ss2 ; x3 = s2^T x2
    { dim3 g(1, (KA + 63) / 64, BATCH); ab_kernel<<<g, 256>>>(S + OFF_ADJ1, S + OFF_S2, S + OFF_TT2, KA, KA, KB); }
    { dim3 g(1, 1, BATCH); atb_kernel<<<g, 256>>>(S + OFF_S2, S + OFF_TT2, S + OFF_ADJR2, KA, KB, KB); }
    { dim3 g(1, 1, BATCH); atb_kernel<<<g, 256>>>(S + OFF_S2, S + OFF_S2, S + OFF_SS2, KA, KB, KB); }
    { dim3 g(1, 1, BATCH); atb_kernel<<<g, 256>>>(S + OFF_S2, S + OFF_X2, S + OFF_X3, KA, KB, HID); }
    // 13) losses + adj2
    loss_norm_kernel<<<BATCH, 128>>>(S + OFF_ADJR2, S + OFF_SS2, S + OFF_S2, S + OFF_DFLAT2,
                                     S + OFF_ADJ2, S + OFF_LOSSB, KB, KA);
    // 14) conv3 (no relu)
    { dim3 g(1, 1, BATCH); ab_kernel<<<g, 256>>>(S + OFF_ADJ2, S + OFF_X3, S + OFF_T3, KB, KB, HID); }
    conv_ep<<<BATCH * KB * 32 / 256, 256>>>(S + OFF_T3, S + OFF_X3, c3rW, c3rb, c3oW, S + OFF_X4, BATCH * KB, 0);
    // 15) head: mean -> lin1 relu -> lin2 -> log_softmax
    head_kernel<<<BATCH, 32>>>(S + OFF_X4, l1W, l1b, l2W, l2b, out);
    // 16) total loss
    final_kernel<<<1, 128>>>(S + OFF_LOSSB, out, out_size);
}

// round 2
// speedup vs baseline: 1.5163x; 1.5163x over previous
#include <cuda_runtime.h>
#include <math.h>

// ---------------------------------------------------------------------------
// Problem constants
// ---------------------------------------------------------------------------
namespace {
constexpr int BATCH = 128, NNODE = 512, INC = 128, HID = 32, KA = 100, KB = 10, OC = 10;
constexpr int KAP = 128;                     // padded KA
constexpr int TOT = BATCH * NNODE;           // 65536
constexpr float EPSV = 1e-15f;

constexpr size_t SZ_ADJ   = (size_t)BATCH * NNODE * NNODE;
constexpr size_t OFF_ADJ  = 0;
constexpr size_t OFF_DEG  = OFF_ADJ + SZ_ADJ;
constexpr size_t OFF_DFLAT= OFF_DEG + TOT;
constexpr size_t OFF_LOSSB= OFF_DFLAT + TOT;
constexpr size_t ZERO_CNT = OFF_LOSSB + BATCH;
constexpr size_t OFF_XWP  = ZERO_CNT;
constexpr size_t OFF_H    = OFF_XWP  + (size_t)TOT * HID;
constexpr size_t OFF_S1   = OFF_H    + (size_t)TOT * HID;          // TOT x 128 (padded)
constexpr size_t OFF_T1   = OFF_S1   + (size_t)TOT * KAP;          // TOT x 128 (padded)
constexpr size_t OFF_ADJR1= OFF_T1   + (size_t)TOT * KAP;          // B x 128 x 128
constexpr size_t OFF_SS1  = OFF_ADJR1+ (size_t)BATCH * KAP * KAP;  // B x 128 x 128
constexpr size_t OFF_X1   = OFF_SS1  + (size_t)BATCH * KAP * KAP;  // B x 100 x 32
constexpr size_t OFF_ADJ1 = OFF_X1   + (size_t)BATCH * KA * HID;   // B x 100 x 100
constexpr size_t OFF_DFLAT2=OFF_ADJ1 + (size_t)BATCH * KA * KA;
constexpr size_t OFF_T2   = OFF_DFLAT2+(size_t)BATCH * KA;
constexpr size_t OFF_X2   = OFF_T2   + (size_t)BATCH * KA * HID;
constexpr size_t OFF_S2   = OFF_X2   + (size_t)BATCH * KA * HID;
constexpr size_t OFF_TT2  = OFF_S2   + (size_t)BATCH * KA * KB;
constexpr size_t OFF_ADJR2= OFF_TT2  + (size_t)BATCH * KA * KB;
constexpr size_t OFF_SS2  = OFF_ADJR2+ (size_t)BATCH * KB * KB;
constexpr size_t OFF_X3   = OFF_SS2  + (size_t)BATCH * KB * KB;
constexpr size_t OFF_ADJ2 = OFF_X3   + (size_t)BATCH * KB * HID;
constexpr size_t OFF_T3   = OFF_ADJ2 + (size_t)BATCH * KB * KB;
constexpr size_t OFF_X4   = OFF_T3   + (size_t)BATCH * KB * HID;
constexpr size_t SCRATCH_TOTAL = OFF_X4 + (size_t)BATCH * KB * HID;
}  // namespace

__device__ __align__(16) float g_scratch[SCRATCH_TOTAL];

// ---------------------------------------------------------------------------
__global__ void zero_kernel(float4* p, size_t n4) {
    size_t i = (size_t)blockIdx.x * blockDim.x + threadIdx.x;
    size_t st = (size_t)gridDim.x * blockDim.x;
    float4 z = make_float4(0.f, 0.f, 0.f, 0.f);
    for (; i < n4; i += st) p[i] = z;
}

__global__ void scatter_kernel(const int* __restrict__ ei, int E,
                               float* __restrict__ adj,
                               float* __restrict__ deg,
                               float* __restrict__ dflat) {
    int e = blockIdx.x * blockDim.x + threadIdx.x;
    if (e >= E) return;
    int s = ei[e];
    int d = ei[E + e];
    int b  = s >> 9;
    int sl = s & 511;
    int dl = d & 511;
    atomicAdd(&adj[((size_t)b << 18) + ((size_t)sl << 9) + dl], 1.0f);
    atomicAdd(&deg[d], 1.0f);
    atomicAdd(&dflat[s], 1.0f);
}

// ---------------------------------------------------------------------------
// xwp[g][c] = rsqrt(deg[g]+1) * sum_k x[g][k] * W[k][c]
// ---------------------------------------------------------------------------
__global__ __launch_bounds__(256) void xwp_kernel(const float* __restrict__ x,
                                                  const float* __restrict__ W,
                                                  const float* __restrict__ deg,
                                                  float* __restrict__ xwp) {
    __shared__ float Ws[INC * HID];
    __shared__ float xs[8][INC];
    int tid = threadIdx.y * 32 + threadIdx.x;
    for (int t = tid; t < INC * HID; t += 256) Ws[t] = W[t];
    int r0 = blockIdx.x * 8;
    for (int t = tid; t < 8 * INC; t += 256) {
        int r = t >> 7, k = t & 127;
        xs[r][k] = x[(size_t)(r0 + r) * INC + k];
    }
    __syncthreads();
    int c = threadIdx.x, r = threadIdx.y;
    float acc = 0.f;
#pragma unroll 8
    for (int k = 0; k < INC; k++) acc += xs[r][k] * Ws[k * HID + c];
    int g = r0 + r;
    float dis = rsqrtf(deg[g] + 1.0f);
    xwp[(size_t)g * HID + c] = dis * acc;
}

// ---------------------------------------------------------------------------
// G1: fused GCN aggregate + epilogue.
// h[i][c] = relu( dis_i * ( (A^T xwp)[i][c] + xwp[i][c] ) + bias[c] )
// per graph: A [512x512] (adj, row n, col i fast), xwp [512x32].
// Tile: 256 rows x 32 cols, 256 threads, micro 8x4. K-tile 16.
// ---------------------------------------------------------------------------
__global__ __launch_bounds__(256) void agg_fused_kernel(const float* __restrict__ adjg,
                                                        const float* __restrict__ xwp,
                                                        const float* __restrict__ deg,
                                                        const float* __restrict__ bias,
                                                        float* __restrict__ h) {
    __shared__ float As[16][256];
    __shared__ float Bs[16][32];
    int b = blockIdx.y;
    int i0 = blockIdx.x * 256;
    const float* A = adjg + ((size_t)b << 18);
    const float* B = xwp + ((size_t)b << 9) * HID;
    int tid = threadIdx.x;
    int tx = tid & 7, ty = tid >> 3;
    float acc[8][4] = {};
    for (int n0 = 0; n0 < NNODE; n0 += 16) {
        // As[kk][ii] <- A[(n0+kk)*512 + i0+ii]  (direct, coalesced, float4)
#pragma unroll
        for (int r = 0; r < 4; r++) {
            int t4 = tid + r * 256;
            int kk = t4 >> 6, iif = (t4 & 63) << 2;
            float4 v = *(const float4*)(A + (size_t)(n0 + kk) * NNODE + i0 + iif);
            *(float4*)&As[kk][iif] = v;
        }
        // Bs[kk][c] <- B[(n0+kk)*32 + c]
        {
            int t4 = tid;
            if (t4 < 128) {
                int kk = t4 >> 3, jf = (t4 & 7) << 2;
                *(float4*)&Bs[kk][jf] = *(const float4*)(B + (n0 + kk) * HID + jf);
            }
        }
        __syncthreads();
#pragma unroll
        for (int kk = 0; kk < 16; kk++) {
            float4 a0 = *(float4*)&As[kk][ty * 8];
            float4 a1 = *(float4*)&As[kk][ty * 8 + 4];
            float4 bb = *(float4*)&Bs[kk][tx * 4];
            float a[8] = {a0.x, a0.y, a0.z, a0.w, a1.x, a1.y, a1.z, a1.w};
            float bv[4] = {bb.x, bb.y, bb.z, bb.w};
#pragma unroll
            for (int u = 0; u < 8; u++)
#pragma unroll
                for (int v = 0; v < 4; v++) acc[u][v] += a[u] * bv[v];
        }
        __syncthreads();
    }
    // fused epilogue
#pragma unroll
    for (int u = 0; u < 8; u++) {
        int g = (b << 9) + i0 + ty * 8 + u;
        float dis = rsqrtf(deg[g] + 1.0f);
        float4 xw = *(const float4*)(xwp + (size_t)g * HID + tx * 4);
        float4 o;
        o.x = fmaxf(dis * (acc[u][0] + xw.x) + bias[tx * 4 + 0], 0.f);
        o.y = fmaxf(dis * (acc[u][1] + xw.y) + bias[tx * 4 + 1], 0.f);
        o.z = fmaxf(dis * (acc[u][2] + xw.z) + bias[tx * 4 + 2], 0.f);
        o.w = fmaxf(dis * (acc[u][3] + xw.w) + bias[tx * 4 + 3], 0.f);
        *(float4*)&h[(size_t)g * HID + tx * 4] = o;
    }
}

// ---------------------------------------------------------------------------
// G2: T1 = A @ s1p  per graph. A [512x512], s1p [512x128], C [512x128].
// Tile 128x128, 256 threads, micro 8x8, K-tile 16. A transposed into smem.
// ---------------------------------------------------------------------------
__global__ __launch_bounds__(256) void t1_kernel(const float* __restrict__ adjg,
                                                 const float* __restrict__ s1p,
                                                 float* __restrict__ T1) {
    __shared__ float As[16][132];   // padded, rows 16B-aligned (132*4=528)
    __shared__ float Bs[16][128];
    int b = blockIdx.y;
    int i0 = blockIdx.x * 128;
    const float* A = adjg + ((size_t)b << 18);
    const float* B = s1p + ((size_t)b << 9) * KAP;
    float* C = T1 + ((size_t)b << 9) * KAP;
    int tid = threadIdx.x;
    int tx = tid & 15, ty = tid >> 4;
    float acc[8][8] = {};
    for (int m0 = 0; m0 < NNODE; m0 += 16) {
        // As[kk][ii] <- A[(i0+ii)*512 + m0+kk]  (transpose during store)
#pragma unroll
        for (int r = 0; r < 2; r++) {
            int t4 = tid + r * 256;
            int ii = t4 >> 2, kkf = (t4 & 3) << 2;
            float4 v = *(const float4*)(A + (size_t)(i0 + ii) * NNODE + m0 + kkf);
            As[kkf + 0][ii] = v.x;
            As[kkf + 1][ii] = v.y;
            As[kkf + 2][ii] = v.z;
            As[kkf + 3][ii] = v.w;
        }
        // Bs[kk][jj] <- B[(m0+kk)*128 + jj]
#pragma unroll
        for (int r = 0; r < 2; r++) {
            int t4 = tid + r * 256;
            int kk = t4 >> 5, jf = (t4 & 31) << 2;
            *(float4*)&Bs[kk][jf] = *(const float4*)(B + (m0 + kk) * KAP + jf);
        }
        __syncthreads();
#pragma unroll
        for (int kk = 0; kk < 16; kk++) {
            float4 a0 = *(float4*)&As[kk][ty * 8];
            float4 a1 = *(float4*)&As[kk][ty * 8 + 4];
            float4 b0 = *(float4*)&Bs[kk][tx * 8];
            float4 b1 = *(float4*)&Bs[kk][tx * 8 + 4];
            float a[8] = {a0.x, a0.y, a0.z, a0.w, a1.x, a1.y, a1.z, a1.w};
            float bv[8] = {b0.x, b0.y, b0.z, b0.w, b1.x, b1.y, b1.z, b1.w};
#pragma unroll
            for (int u = 0; u < 8; u++)
#pragma unroll
                for (int v = 0; v < 8; v++) acc[u][v] += a[u] * bv[v];
        }
        __syncthreads();
    }
#pragma unroll
    for (int u = 0; u < 8; u++) {
        int row = i0 + ty * 8 + u;
        float4 o0 = make_float4(acc[u][0], acc[u][1], acc[u][2], acc[u][3]);
        float4 o1 = make_float4(acc[u][4], acc[u][5], acc[u][6], acc[u][7]);
        *(float4*)&C[(size_t)row * KAP + tx * 8] = o0;
        *(float4*)&C[(size_t)row * KAP + tx * 8 + 4] = o1;
    }
}

// ---------------------------------------------------------------------------
// G3a: C = s1p^T @ B, all dims 128 padded, K=512.
// blockIdx.x: 0 -> B=T1 (C=adjr1), 1 -> B=s1p (C=ss1)
// ---------------------------------------------------------------------------
__global__ __launch_bounds__(256) void atb8_128_kernel(const float* __restrict__ s1p,
                                                       const float* __restrict__ T1,
                                                       float* __restrict__ adjr1,
                                                       float* __restrict__ ss1) {
    __shared__ float As[16][128];
    __shared__ float Bs[16][128];
    int b = blockIdx.y;
    int sel = blockIdx.x;
    const float* A = s1p + ((size_t)b << 9) * KAP;
    const float* B = (sel ? s1p : T1) + ((size_t)b << 9) * KAP;
    float* C = (sel ? ss1 : adjr1) + (size_t)b * KAP * KAP;
    int tid = threadIdx.x;
    int tx = tid & 15, ty = tid >> 4;
    float acc[8][8] = {};
    for (int n0 = 0; n0 < NNODE; n0 += 16) {
#pragma unroll
        for (int r = 0; r < 2; r++) {
            int t4 = tid + r * 256;
            int kk = t4 >> 5, jf = (t4 & 31) << 2;
            *(float4*)&As[kk][jf] = *(const float4*)(A + (n0 + kk) * KAP + jf);
            *(float4*)&Bs[kk][jf] = *(const float4*)(B + (n0 + kk) * KAP + jf);
        }
        __syncthreads();
#pragma unroll
        for (int kk = 0; kk < 16; kk++) {
            float4 a0 = *(float4*)&As[kk][ty * 8];
            float4 a1 = *(float4*)&As[kk][ty * 8 + 4];
            float4 b0 = *(float4*)&Bs[kk][tx * 8];
            float4 b1 = *(float4*)&Bs[kk][tx * 8 + 4];
            float a[8] = {a0.x, a0.y, a0.z, a0.w, a1.x, a1.y, a1.z, a1.w};
            float bv[8] = {b0.x, b0.y, b0.z, b0.w, b1.x, b1.y, b1.z, b1.w};
#pragma unroll
            for (int u = 0; u < 8; u++)
#pragma unroll
                for (int v = 0; v < 8; v++) acc[u][v] += a[u] * bv[v];
        }
        __syncthreads();
    }
#pragma unroll
    for (int u = 0; u < 8; u++) {
        int row = ty * 8 + u;
        float4 o0 = make_float4(acc[u][0], acc[u][1], acc[u][2], acc[u][3]);
        float4 o1 = make_float4(acc[u][4], acc[u][5], acc[u][6], acc[u][7]);
        *(float4*)&C[(size_t)row * KAP + tx * 8] = o0;
        *(float4*)&C[(size_t)row * KAP + tx * 8 + 4] = o1;
    }
}

// ---------------------------------------------------------------------------
// G3b: x1 = s1p^T @ h, I=128 (write <100), J=32, K=512. micro 4x4.
// ---------------------------------------------------------------------------
__global__ __launch_bounds__(256) void atb8_32_kernel(const float* __restrict__ s1p,
                                                      const float* __restrict__ h,
                                                      float* __restrict__ x1) {
    __shared__ float As[16][128];
    __shared__ float Bs[16][32];
    int b = blockIdx.x;
    const float* A = s1p + ((size_t)b << 9) * KAP;
    const float* B = h + ((size_t)b << 9) * HID;
    float* C = x1 + (size_t)b * KA * HID;
    int tid = threadIdx.x;
    int tx = tid & 7, ty = tid >> 3;
    float acc[4][4] = {};
    for (int n0 = 0; n0 < NNODE; n0 += 16) {
#pragma unroll
        for (int r = 0; r < 2; r++) {
            int t4 = tid + r * 256;
            int kk = t4 >> 5, jf = (t4 & 31) << 2;
            *(float4*)&As[kk][jf] = *(const float4*)(A + (n0 + kk) * KAP + jf);
        }
        if (tid < 128) {
            int kk = tid >> 3, jf = (tid & 7) << 2;
            *(float4*)&Bs[kk][jf] = *(const float4*)(B + (n0 + kk) * HID + jf);
        }
        __syncthreads();
#pragma unroll
        for (int kk = 0; kk < 16; kk++) {
            float4 av = *(float4*)&As[kk][ty * 4];
            float4 bb = *(float4*)&Bs[kk][tx * 4];
            float a[4] = {av.x, av.y, av.z, av.w};
            float bv[4] = {bb.x, bb.y, bb.z, bb.w};
#pragma unroll
            for (int u = 0; u < 4; u++)
#pragma unroll
                for (int v = 0; v < 4; v++) acc[u][v] += a[u] * bv[v];
        }
        __syncthreads();
    }
#pragma unroll
    for (int u = 0; u < 4; u++) {
        int row = ty * 4 + u;
        if (row < KA)
            *(float4*)&C[(size_t)row * HID + tx * 4] =
                make_float4(acc[u][0], acc[u][1], acc[u][2], acc[u][3]);
    }
}

// ---------------------------------------------------------------------------
// small GEMMs (stage 2): original 64-tile kernels
// ---------------------------------------------------------------------------
__global__ __launch_bounds__(256) void atb_kernel(const float* __restrict__ A,
                                                  const float* __restrict__ Bm,
                                                  float* __restrict__ C,
                                                  int n, int I, int J) {
    int b = blockIdx.z;
    A  += (size_t)b * n * I;
    Bm += (size_t)b * n * J;
    C  += (size_t)b * I * J;
    __shared__ float As[16][64];
    __shared__ float Bs[16][64];
    int i0 = blockIdx.y * 64, j0 = blockIdx.x * 64;
    int tid = threadIdx.x;
    int tx = tid & 15, ty = tid >> 4;
    float acc[4][4] = {};
    for (int n0 = 0; n0 < n; n0 += 16) {
        for (int t = tid; t < 16 * 64; t += 256) {
            int kk = t >> 6, ii = t & 63;
            int nn = n0 + kk;
            As[kk][ii] = (nn < n && i0 + ii < I) ? A[(size_t)nn * I + i0 + ii] : 0.f;
            Bs[kk][ii] = (nn < n && j0 + ii < J) ? Bm[(size_t)nn * J + j0 + ii] : 0.f;
        }
        __syncthreads();
#pragma unroll
        for (int kk = 0; kk < 16; kk++) {
            float a[4], bb[4];
#pragma unroll
            for (int u = 0; u < 4; u++) { a[u] = As[kk][ty * 4 + u]; bb[u] = Bs[kk][tx * 4 + u]; }
#pragma unroll
            for (int u = 0; u < 4; u++)
#pragma unroll
                for (int v = 0; v < 4; v++) acc[u][v] += a[u] * bb[v];
        }
        __syncthreads();
    }
#pragma unroll
    for (int u = 0; u < 4; u++) {
        int i = i0 + ty * 4 + u;
        if (i >= I) continue;
#pragma unroll
        for (int v = 0; v < 4; v++) {
            int j = j0 + tx * 4 + v;
            if (j < J) C[(size_t)i * J + j] = acc[u][v];
        }
    }
}

__global__ __launch_bounds__(256) void ab_kernel(const float* __restrict__ A,
                                                 const float* __restrict__ Bm,
                                                 float* __restrict__ C,
                                                 int I, int M, int J) {
    int b = blockIdx.z;
    A  += (size_t)b * I * M;
    Bm += (size_t)b * M * J;
    C  += (size_t)b * I * J;
    __shared__ float As[16][64];
    __shared__ float Bs[16][64];
    int i0 = blockIdx.y * 64, j0 = blockIdx.x * 64;
    int tid = threadIdx.x;
    int tx = tid & 15, ty = tid >> 4;
    float acc[4][4] = {};
    for (int m0 = 0; m0 < M; m0 += 16) {
        for (int t = tid; t < 16 * 64; t += 256) {
            int kk = t & 15, ii = t >> 4;
            As[kk][ii] = (m0 + kk < M && i0 + ii < I) ? A[(size_t)(i0 + ii) * M + m0 + kk] : 0.f;
            int kk2 = t >> 6, jj = t & 63;
            Bs[kk2][jj] = (m0 + kk2 < M && j0 + jj < J) ? Bm[(size_t)(m0 + kk2) * J + j0 + jj] : 0.f;
        }
        __syncthreads();
#pragma unroll
        for (int kk = 0; kk < 16; kk++) {
            float a[4], bb[4];
#pragma unroll
            for (int u = 0; u < 4; u++) { a[u] = As[kk][ty * 4 + u]; bb[u] = Bs[kk][tx * 4 + u]; }
#pragma unroll
            for (int u = 0; u < 4; u++)
#pragma unroll
                for (int v = 0; v < 4; v++) acc[u][v] += a[u] * bb[v];
        }
        __syncthreads();
    }
#pragma unroll
    for (int u = 0; u < 4; u++) {
        int i = i0 + ty * 4 + u;
        if (i >= I) continue;
#pragma unroll
        for (int v = 0; v < 4; v++) {
            int j = j0 + tx * 4 + v;
            if (j < J) C[(size_t)i * J + j] = acc[u][v];
        }
    }
}

// ---------------------------------------------------------------------------
// S = softmax(X @ W + b) with padded output leading dim (zeros in pad cols)
// ---------------------------------------------------------------------------
__global__ void pool_softmax(const float* __restrict__ X, const float* __restrict__ W,
                             const float* __restrict__ bias, float* __restrict__ Sout,
                             int rows, int K, int ldout) {
    int gw = (blockIdx.x * blockDim.x + threadIdx.x) >> 5;
    int lane = threadIdx.x & 31;
    if (gw >= rows) return;
    float xv = X[(size_t)gw * HID + lane];
    int slots = (ldout + 31) >> 5;
    float vals[4];
    float mx = -INFINITY;
    for (int t = 0; t < slots; t++) {
        int k = t * 32 + lane;
        float acc = 0.f;
#pragma unroll
        for (int c = 0; c < HID; c++) {
            float w = (k < K) ? W[c * K + k] : 0.f;
            acc += __shfl_sync(0xffffffffu, xv, c) * w;
        }
        float v = (k < K) ? acc + bias[k] : -INFINITY;
        vals[t] = v;
        mx = fmaxf(mx, v);
    }
#pragma unroll
    for (int o = 16; o; o >>= 1) mx = fmaxf(mx, __shfl_xor_sync(0xffffffffu, mx, o));
    float sum = 0.f;
    for (int t = 0; t < slots; t++) {
        int k = t * 32 + lane;
        float e = (k < K) ? expf(vals[t] - mx) : 0.f;
        vals[t] = e;
        sum += e;
    }
#pragma unroll
    for (int o = 16; o; o >>= 1) sum += __shfl_xor_sync(0xffffffffu, sum, o);
    float inv = 1.0f / sum;
    for (int t = 0; t < slots; t++) {
        int k = t * 32 + lane;
        if (k < ldout) Sout[(size_t)gw * ldout + k] = (k < K) ? vals[t] * inv : 0.f;
    }
}

// ---------------------------------------------------------------------------
__device__ __forceinline__ float blockReduce128(float v, float* sm) {
    int t = threadIdx.x;
    sm[t] = v;
    __syncthreads();
    for (int s = 64; s > 0; s >>= 1) {
        if (t < s) sm[t] += sm[t + s];
        __syncthreads();
    }
    float r = sm[0];
    __syncthreads();
    return r;
}

__global__ void loss_norm_kernel(const float* __restrict__ raw,
                                 const float* __restrict__ ss,
                                 const float* __restrict__ s,
                                 const float* __restrict__ dflat,
                                 float* __restrict__ adjn,
                                 float* __restrict__ lossb,
                                 int k, int n, int ld, int ld_s) {
    int b = blockIdx.x;
    raw  += (size_t)b * k * ld;       // note: padded storage b*ld*ld when ld>k
    ss   += (size_t)b * k * ld;
    s    += (size_t)b * n * ld_s;
    dflat+= (size_t)b * n;
    adjn += (size_t)b * k * k;
    // adjust for padded layouts: when ld != k the per-batch stride is ld*ld
    if (ld != k) {
        raw += (size_t)b * (ld - k) * ld;
        ss  += (size_t)b * (ld - k) * ld;
    }
    __shared__ float sm[128];
    __shared__ float dc[128];
    int tid = threadIdx.x;

    float v = 0.f;
    for (int i = tid; i < k; i += 128) v += raw[i * ld + i];
    float num = blockReduce128(v, sm);

    v = 0.f;
    for (int nn = tid; nn < n; nn += 128) {
        float dv = dflat[nn];
        float acc = 0.f;
        for (int kk = 0; kk < k; kk++) {
            float sv = s[(size_t)nn * ld_s + kk];
            acc += sv * sv;
        }
        v += acc * dv;
    }
    float den = blockReduce128(v, sm);

    v = 0.f;
    for (int i = tid; i < k; i += 128)
        for (int j = 0; j < k; j++) { float t = ss[i * ld + j]; v += t * t; }
    float nrm = sqrtf(blockReduce128(v, sm));

    float invn = 1.0f / nrm;
    float dk = rsqrtf((float)k);
    v = 0.f;
    for (int i = tid; i < k; i += 128)
        for (int j = 0; j < k; j++) {
            float t = ss[i * ld + j] * invn - ((i == j) ? dk : 0.f);
            v += t * t;
        }
    float ortho = sqrtf(blockReduce128(v, sm));

    for (int i = tid; i < k; i += 128) {
        float r = 0.f;
        for (int j = 0; j < k; j++) if (j != i) r += raw[i * ld + j];
        dc[i] = sqrtf(r) + EPSV;
    }
    __syncthreads();
    for (int idx = tid; idx < k * k; idx += 128) {
        int i = idx / k, j = idx - i * k;
        adjn[idx] = (i == j) ? 0.f : raw[i * ld + j] / (dc[i] * dc[j]);
    }
    if (tid == 0) lossb[b] += -num / den + ortho;
}

// ---------------------------------------------------------------------------
__global__ void rowsum_kernel(const float* __restrict__ A, float* __restrict__ out,
                              int rows, int len) {
    int idx = blockIdx.x * blockDim.x + threadIdx.x;
    if (idx >= rows) return;
    const float* r = A + (size_t)idx * len;
    float v = 0.f;
    for (int j = 0; j < len; j++) v += r[j];
    out[idx] = v;
}

__global__ void conv_ep(const float* __restrict__ t, const float* __restrict__ xin,
                        const float* __restrict__ relW, const float* __restrict__ relb,
                        const float* __restrict__ rootW, float* __restrict__ out,
                        int rows, int do_relu) {
    int w = (blockIdx.x * blockDim.x + threadIdx.x) >> 5;
    int lane = threadIdx.x & 31;
    if (w >= rows) return;
    float tv = t[(size_t)w * HID + lane];
    float xv = xin[(size_t)w * HID + lane];
    float acc = relb[lane];
#pragma unroll
    for (int kk = 0; kk < HID; kk++) {
        acc += __shfl_sync(0xffffffffu, tv, kk) * relW[kk * HID + lane]
             + __shfl_sync(0xffffffffu, xv, kk) * rootW[kk * HID + lane];
    }
    if (do_relu) acc = fmaxf(acc, 0.f);
    out[(size_t)w * HID + lane] = acc;
}

__global__ void head_kernel(const float* __restrict__ x4,
                            const float* __restrict__ l1W, const float* __restrict__ l1b,
                            const float* __restrict__ l2W, const float* __restrict__ l2b,
                            float* __restrict__ out) {
    int b = blockIdx.x, lane = threadIdx.x;
    const float* xb = x4 + (size_t)b * KB * HID;
    float g = 0.f;
#pragma unroll
    for (int r = 0; r < KB; r++) g += xb[r * HID + lane];
    g *= (1.0f / KB);
    float acc = l1b[lane];
#pragma unroll
    for (int kk = 0; kk < HID; kk++) acc += __shfl_sync(0xffffffffu, g, kk) * l1W[kk * HID + lane];
    float gg = fmaxf(acc, 0.f);
    float acc2 = (lane < OC) ? l2b[lane] : 0.f;
#pragma unroll
    for (int kk = 0; kk < HID; kk++) {
        float w = (lane < OC) ? l2W[kk * OC + lane] : 0.f;
        acc2 += __shfl_sync(0xffffffffu, gg, kk) * w;
    }
    float val = (lane < OC) ? acc2 : -INFINITY;
    float m = val;
#pragma unroll
    for (int o = 16; o; o >>= 1) m = fmaxf(m, __shfl_xor_sync(0xffffffffu, m, o));
    float e = (lane < OC) ? expf(val - m) : 0.f;
    float ssum = e;
#pragma unroll
    for (int o = 16; o; o >>= 1) ssum += __shfl_xor_sync(0xffffffffu, ssum, o);
    if (lane < OC) out[b * OC + lane] = val - m - logf(ssum);
}

__global__ void final_kernel(const float* __restrict__ lossb, float* __restrict__ out,
                             int out_size) {
    __shared__ float sm[128];
    int t = threadIdx.x;
    sm[t] = lossb[t];
    __syncthreads();
    for (int s = 64; s > 0; s >>= 1) {
        if (t < s) sm[t] += sm[t + s];
        __syncthreads();
    }
    if (t == 0 && out_size > BATCH * OC) out[BATCH * OC] = sm[0] / (float)BATCH;
}

// ---------------------------------------------------------------------------
extern "C" void kernel_launch(void* const* d_in, const int* in_sizes, int n_in,
                              void* d_out, int out_size) {
    const float* x    = (const float*)d_in[0];
    const int*   ei   = (const int*)  d_in[1];
    const float* c1W  = (const float*)d_in[3];
    const float* c1b  = (const float*)d_in[4];
    const float* p1W  = (const float*)d_in[5];
    const float* p1b  = (const float*)d_in[6];
    const float* c2rW = (const float*)d_in[7];
    const float* c2rb = (const float*)d_in[8];
    const float* c2oW = (const float*)d_in[9];
    const float* p2W  = (const float*)d_in[10];
    const float* p2b  = (const float*)d_in[11];
    const float* c3rW = (const float*)d_in[12];
    const float* c3rb = (const float*)d_in[13];
    const float* c3oW = (const float*)d_in[14];
    const float* l1W  = (const float*)d_in[15];
    const float* l1b  = (const float*)d_in[16];
    const float* l2W  = (const float*)d_in[17];
    const float* l2b  = (const float*)d_in[18];
    float* out = (float*)d_out;
    int E = in_sizes[1] / 2;

    void* sp = nullptr;
    cudaGetSymbolAddress(&sp, g_scratch);
    float* S = (float*)sp;
    float* adj = S + OFF_ADJ;

    zero_kernel<<<4096, 256>>>((float4*)S, ZERO_CNT / 4);
    scatter_kernel<<<(E + 255) / 256, 256>>>(ei, E, adj, S + OFF_DEG, S + OFF_DFLAT);
    xwp_kernel<<<TOT / 8, dim3(32, 8)>>>(x, c1W, S + OFF_DEG, S + OFF_XWP);
    { dim3 g(2, BATCH); agg_fused_kernel<<<g, 256>>>(adj, S + OFF_XWP, S + OFF_DEG, c1b, S + OFF_H); }
    pool_softmax<<<TOT * 32 / 256, 256>>>(S + OFF_H, p1W, p1b, S + OFF_S1, TOT, KA, KAP);
    { dim3 g(4, BATCH); t1_kernel<<<g, 256>>>(adj, S + OFF_S1, S + OFF_T1); }
    { dim3 g(2, BATCH); atb8_128_kernel<<<g, 256>>>(S + OFF_S1, S + OFF_T1, S + OFF_ADJR1, S + OFF_SS1); }
    atb8_32_kernel<<<BATCH, 256>>>(S + OFF_S1, S + OFF_H, S + OFF_X1);
    loss_norm_kernel<<<BATCH, 128>>>(S + OFF_ADJR1, S + OFF_SS1, S + OFF_S1, S + OFF_DFLAT,
                                     S + OFF_ADJ1, S + OFF_LOSSB, KA, NNODE, KAP, KAP);
    rowsum_kernel<<<(BATCH * KA + 255) / 256, 256>>>(S + OFF_ADJ1, S + OFF_DFLAT2, BATCH * KA, KA);
    { dim3 g(1, 2, BATCH); ab_kernel<<<g, 256>>>(S + OFF_ADJ1, S + OFF_X1, S + OFF_T2, KA, KA, HID); }
    conv_ep<<<BATCH * KA * 32 / 256, 256>>>(S + OFF_T2, S + OFF_X1, c2rW, c2rb, c2oW, S + OFF_X2, BATCH * KA, 1);
    pool_softmax<<<BATCH * KA * 32 / 256, 256>>>(S + OFF_X2, p2W, p2b, S + OFF_S2, BATCH * KA, KB, KB);
    { dim3 g(1, 2, BATCH); ab_kernel<<<g, 256>>>(S + OFF_ADJ1, S + OFF_S2, S + OFF_TT2, KA, KA, KB); }
    { dim3 g(1, 1, BATCH); atb_kernel<<<g, 256>>>(S + OFF_S2, S + OFF_TT2, S + OFF_ADJR2, KA, KB, KB); }
    { dim3 g(1, 1, BATCH); atb_kernel<<<g, 256>>>(S + OFF_S2, S + OFF_S2, S + OFF_SS2, KA, KB, KB); }
    { dim3 g(1, 1, BATCH); atb_kernel<<<g, 256>>>(S + OFF_S2, S + OFF_X2, S + OFF_X3, KA, KB, HID); }
    loss_norm_kernel<<<BATCH, 128>>>(S + OFF_ADJR2, S + OFF_SS2, S + OFF_S2, S + OFF_DFLAT2,
                                     S + OFF_ADJ2, S + OFF_LOSSB, KB, KA, KB, KB);
    { dim3 g(1, 1, BATCH); ab_kernel<<<g, 256>>>(S + OFF_ADJ2, S + OFF_X3, S + OFF_T3, KB, KB, HID); }
    conv_ep<<<BATCH * KB * 32 / 256, 256>>>(S + OFF_T3, S + OFF_X3, c3rW, c3rb, c3oW, S + OFF_X4, BATCH * KB, 0);
    head_kernel<<<BATCH, 32>>>(S + OFF_X4, l1W, l1b, l2W, l2b, out);
    final_kernel<<<1, 128>>>(S + OFF_LOSSB, out, out_size);
}

// round 3
// speedup vs baseline: 1.6314x; 1.0759x over previous
#include <cuda_runtime.h>
#include <math.h>

namespace {
constexpr int BATCH = 128, NNODE = 512, INC = 128, HID = 32, KA = 100, KB = 10, OC = 10;
constexpr int KAP = 128;
constexpr int TOT = BATCH * NNODE;
constexpr float EPSV = 1e-15f;

constexpr size_t OFF_DEG    = 0;
constexpr size_t OFF_DFLAT  = OFF_DEG + TOT;
constexpr size_t OFF_LOSSB  = OFF_DFLAT + TOT;
constexpr size_t ZERO_CNT   = OFF_LOSSB + BATCH;                    // 131200, /4 ok
constexpr size_t OFF_XWP    = ZERO_CNT;
constexpr size_t OFF_H      = OFF_XWP   + (size_t)TOT * HID;
constexpr size_t OFF_S1     = OFF_H     + (size_t)TOT * HID;
constexpr size_t OFF_T1     = OFF_S1    + (size_t)TOT * KAP;
constexpr size_t OFF_ADJR1  = OFF_T1    + (size_t)TOT * KAP;
constexpr size_t OFF_SS1    = OFF_ADJR1 + (size_t)BATCH * KAP * KAP;
constexpr size_t OFF_X1     = OFF_SS1   + (size_t)BATCH * KAP * KAP;
constexpr size_t OFF_ADJ1   = OFF_X1    + (size_t)BATCH * KA * HID;
constexpr size_t OFF_DFLAT2 = OFF_ADJ1  + (size_t)BATCH * KA * KA;
constexpr size_t OFF_DUMMY  = OFF_DFLAT2+ (size_t)BATCH * KA;
constexpr size_t OFF_X2     = OFF_DUMMY + (size_t)BATCH * KB;
constexpr size_t OFF_S2     = OFF_X2    + (size_t)BATCH * KA * HID;
constexpr size_t OFF_ADJR2  = OFF_S2    + (size_t)BATCH * KA * KB;
constexpr size_t OFF_SS2    = OFF_ADJR2 + (size_t)BATCH * KB * KB;
constexpr size_t OFF_X3     = OFF_SS2   + (size_t)BATCH * KB * KB;
constexpr size_t OFF_ADJ2   = OFF_X3    + (size_t)BATCH * KB * HID;
constexpr size_t SCRATCH_TOTAL = OFF_ADJ2 + (size_t)BATCH * KB * KB;
}  // namespace

__device__ __align__(16) float g_scratch[SCRATCH_TOTAL];

// ---------------------------------------------------------------------------
__global__ void zero_kernel(float4* p, size_t n4) {
    size_t i = (size_t)blockIdx.x * blockDim.x + threadIdx.x;
    size_t st = (size_t)gridDim.x * blockDim.x;
    float4 z = make_float4(0.f, 0.f, 0.f, 0.f);
    for (; i < n4; i += st) p[i] = z;
}

// degrees only (no dense adjacency)
__global__ void scatter_kernel(const int* __restrict__ ei, int E,
                               float* __restrict__ deg,
                               float* __restrict__ dflat) {
    int e = blockIdx.x * blockDim.x + threadIdx.x;
    if (e >= E) return;
    int s = ei[e];
    int d = ei[E + e];
    atomicAdd(&deg[d], 1.0f);
    atomicAdd(&dflat[s], 1.0f);
}

// ---------------------------------------------------------------------------
// xwp[g][c] = rsqrt(deg[g]+1) * (x @ conv1_W)[g][c]
// ---------------------------------------------------------------------------
__global__ __launch_bounds__(256) void xwp_kernel(const float* __restrict__ x,
                                                  const float* __restrict__ W,
                                                  const float* __restrict__ deg,
                                                  float* __restrict__ xwp) {
    __shared__ float Ws[INC * HID];
    __shared__ float xs[8][INC];
    int tid = threadIdx.y * 32 + threadIdx.x;
    for (int t = tid; t < INC * HID; t += 256) Ws[t] = W[t];
    int r0 = blockIdx.x * 8;
    for (int t = tid; t < 8 * INC; t += 256) {
        int r = t >> 7, k = t & 127;
        xs[r][k] = x[(size_t)(r0 + r) * INC + k];
    }
    __syncthreads();
    int c = threadIdx.x, r = threadIdx.y;
    float acc = 0.f;
#pragma unroll 8
    for (int k = 0; k < INC; k++) acc += xs[r][k] * Ws[k * HID + c];
    int g = r0 + r;
    float dis = rsqrtf(deg[g] + 1.0f);
    xwp[(size_t)g * HID + c] = dis * acc;
}

// ---------------------------------------------------------------------------
// Sparse GCN aggregate + fused epilogue. One block per graph.
// smem acc[512][32]; per edge (s->d): acc[d][:] += xwp[s][:]
// then h = relu(dis_d*(acc[d]+xwp[d]) + bias)
// ---------------------------------------------------------------------------
__global__ __launch_bounds__(512) void agg_sparse_kernel(
    const int* __restrict__ ei, int Etot, int eper,
    const float* __restrict__ xwp, const float* __restrict__ deg,
    const float* __restrict__ bias, float* __restrict__ h) {
    extern __shared__ float acc[];   // 512*32 floats = 64 KB
    int b = blockIdx.x, tid = threadIdx.x;
    float4* a4 = (float4*)acc;
    for (int i = tid; i < 512 * 32 / 4; i += 512) a4[i] = make_float4(0, 0, 0, 0);
    __syncthreads();
    int lane = tid & 31, warp = tid >> 5;   // 16 warps
    const int* srcp = ei + (size_t)b * eper;
    const int* dstp = ei + Etot + (size_t)b * eper;
    const float* xb = xwp + (((size_t)b << 9) << 5);
    for (int e0 = warp * 4; e0 < eper; e0 += 64) {
        int s[4], d[4];
        float v[4];
#pragma unroll
        for (int q = 0; q < 4; q++) {
            int e = e0 + q;
            if (e < eper) {
                s[q] = srcp[e] & 511;
                d[q] = dstp[e] & 511;
                v[q] = xb[(s[q] << 5) + lane];
            } else d[q] = -1;
        }
#pragma unroll
        for (int q = 0; q < 4; q++)
            if (d[q] >= 0) atomicAdd(&acc[(d[q] << 5) + lane], v[q]);
    }
    __syncthreads();
    float bb = bias[lane];
    for (int r = warp; r < 512; r += 16) {
        int g = (b << 9) + r;
        float dis = rsqrtf(deg[g] + 1.0f);
        float xv = xb[(r << 5) + lane];
        h[((size_t)g << 5) + lane] = fmaxf(dis * (acc[(r << 5) + lane] + xv) + bb, 0.f);
    }
}

// ---------------------------------------------------------------------------
// Sparse T1 = A @ s1p. Grid (4, BATCH): 32-column quarter per block.
// per edge (s->d): acc[s][j0:j0+32] += s1p[d][j0:j0+32]
// ---------------------------------------------------------------------------
__global__ __launch_bounds__(512) void t1_sparse_kernel(
    const int* __restrict__ ei, int Etot, int eper,
    const float* __restrict__ s1p, float* __restrict__ T1) {
    extern __shared__ float acc[];   // 512*32 floats = 64 KB
    int b = blockIdx.y, j0 = blockIdx.x << 5, tid = threadIdx.x;
    float4* a4 = (float4*)acc;
    for (int i = tid; i < 512 * 32 / 4; i += 512) a4[i] = make_float4(0, 0, 0, 0);
    __syncthreads();
    int lane = tid & 31, warp = tid >> 5;
    const int* srcp = ei + (size_t)b * eper;
    const int* dstp = ei + Etot + (size_t)b * eper;
    const float* sb = s1p + (((size_t)b << 9) << 7) + j0;
    for (int e0 = warp * 4; e0 < eper; e0 += 64) {
        int s[4], d[4];
        float v[4];
#pragma unroll
        for (int q = 0; q < 4; q++) {
            int e = e0 + q;
            if (e < eper) {
                s[q] = srcp[e] & 511;
                d[q] = dstp[e] & 511;
                v[q] = sb[(d[q] << 7) + lane];
            } else s[q] = -1;
        }
#pragma unroll
        for (int q = 0; q < 4; q++)
            if (s[q] >= 0) atomicAdd(&acc[(s[q] << 5) + lane], v[q]);
    }
    __syncthreads();
    for (int r = warp; r < 512; r += 16)
        T1[((((size_t)b << 9) + r) << 7) + j0 + lane] = acc[(r << 5) + lane];
}

// ---------------------------------------------------------------------------
// adjr1 = s1^T T1, ss1 = s1^T s1 (128x128 padded, K=512). micro 8x8.
// ---------------------------------------------------------------------------
__global__ __launch_bounds__(256) void atb8_128_kernel(const float* __restrict__ s1p,
                                                       const float* __restrict__ T1,
                                                       float* __restrict__ adjr1,
                                                       float* __restrict__ ss1) {
    __shared__ float As[16][128];
    __shared__ float Bs[16][128];
    int b = blockIdx.y;
    int sel = blockIdx.x;
    const float* A = s1p + ((size_t)b << 9) * KAP;
    const float* B = (sel ? s1p : T1) + ((size_t)b << 9) * KAP;
    float* C = (sel ? ss1 : adjr1) + (size_t)b * KAP * KAP;
    int tid = threadIdx.x;
    int tx = tid & 15, ty = tid >> 4;
    float acc[8][8] = {};
    for (int n0 = 0; n0 < NNODE; n0 += 16) {
#pragma unroll
        for (int r = 0; r < 2; r++) {
            int t4 = tid + r * 256;
            int kk = t4 >> 5, jf = (t4 & 31) << 2;
            *(float4*)&As[kk][jf] = *(const float4*)(A + (n0 + kk) * KAP + jf);
            *(float4*)&Bs[kk][jf] = *(const float4*)(B + (n0 + kk) * KAP + jf);
        }
        __syncthreads();
#pragma unroll
        for (int kk = 0; kk < 16; kk++) {
            float4 a0 = *(float4*)&As[kk][ty * 8];
            float4 a1 = *(float4*)&As[kk][ty * 8 + 4];
            float4 b0 = *(float4*)&Bs[kk][tx * 8];
            float4 b1 = *(float4*)&Bs[kk][tx * 8 + 4];
            float a[8] = {a0.x, a0.y, a0.z, a0.w, a1.x, a1.y, a1.z, a1.w};
            float bv[8] = {b0.x, b0.y, b0.z, b0.w, b1.x, b1.y, b1.z, b1.w};
#pragma unroll
            for (int u = 0; u < 8; u++)
#pragma unroll
                for (int v = 0; v < 8; v++) acc[u][v] += a[u] * bv[v];
        }
        __syncthreads();
    }
#pragma unroll
    for (int u = 0; u < 8; u++) {
        int row = ty * 8 + u;
        *(float4*)&C[(size_t)row * KAP + tx * 8] =
            make_float4(acc[u][0], acc[u][1], acc[u][2], acc[u][3]);
        *(float4*)&C[(size_t)row * KAP + tx * 8 + 4] =
            make_float4(acc[u][4], acc[u][5], acc[u][6], acc[u][7]);
    }
}

// ---------------------------------------------------------------------------
// x1 = s1^T h  (I=128 pad -> write <100, J=32, K=512)
// ---------------------------------------------------------------------------
__global__ __launch_bounds__(256) void atb8_32_kernel(const float* __restrict__ s1p,
                                                      const float* __restrict__ h,
                                                      float* __restrict__ x1) {
    __shared__ float As[16][128];
    __shared__ float Bs[16][32];
    int b = blockIdx.x;
    const float* A = s1p + ((size_t)b << 9) * KAP;
    const float* B = h + ((size_t)b << 9) * HID;
    float* C = x1 + (size_t)b * KA * HID;
    int tid = threadIdx.x;
    int tx = tid & 7, ty = tid >> 3;
    float acc[4][4] = {};
    for (int n0 = 0; n0 < NNODE; n0 += 16) {
#pragma unroll
        for (int r = 0; r < 2; r++) {
            int t4 = tid + r * 256;
            int kk = t4 >> 5, jf = (t4 & 31) << 2;
            *(float4*)&As[kk][jf] = *(const float4*)(A + (n0 + kk) * KAP + jf);
        }
        if (tid < 128) {
            int kk = tid >> 3, jf = (tid & 7) << 2;
            *(float4*)&Bs[kk][jf] = *(const float4*)(B + (n0 + kk) * HID + jf);
        }
        __syncthreads();
#pragma unroll
        for (int kk = 0; kk < 16; kk++) {
            float4 av = *(float4*)&As[kk][ty * 4];
            float4 bb = *(float4*)&Bs[kk][tx * 4];
            float a[4] = {av.x, av.y, av.z, av.w};
            float bv[4] = {bb.x, bb.y, bb.z, bb.w};
#pragma unroll
            for (int u = 0; u < 4; u++)
#pragma unroll
                for (int v = 0; v < 4; v++) acc[u][v] += a[u] * bv[v];
        }
        __syncthreads();
    }
#pragma unroll
    for (int u = 0; u < 4; u++) {
        int row = ty * 4 + u;
        if (row < KA)
            *(float4*)&C[(size_t)row * HID + tx * 4] =
                make_float4(acc[u][0], acc[u][1], acc[u][2], acc[u][3]);
    }
}

// ---------------------------------------------------------------------------
// S = softmax(X @ W + b), padded output ld (zeros in pad cols)
// ---------------------------------------------------------------------------
__global__ void pool_softmax(const float* __restrict__ X, const float* __restrict__ W,
                             const float* __restrict__ bias, float* __restrict__ Sout,
                             int rows, int K, int ldout) {
    int gw = (blockIdx.x * blockDim.x + threadIdx.x) >> 5;
    int lane = threadIdx.x & 31;
    if (gw >= rows) return;
    float xv = X[(size_t)gw * HID + lane];
    int slots = (ldout + 31) >> 5;
    float vals[4];
    float mx = -INFINITY;
    for (int t = 0; t < slots; t++) {
        int k = t * 32 + lane;
        float acc = 0.f;
#pragma unroll
        for (int c = 0; c < HID; c++) {
            float w = (k < K) ? W[c * K + k] : 0.f;
            acc += __shfl_sync(0xffffffffu, xv, c) * w;
        }
        float v = (k < K) ? acc + bias[k] : -INFINITY;
        vals[t] = v;
        mx = fmaxf(mx, v);
    }
#pragma unroll
    for (int o = 16; o; o >>= 1) mx = fmaxf(mx, __shfl_xor_sync(0xffffffffu, mx, o));
    float sum = 0.f;
    for (int t = 0; t < slots; t++) {
        int k = t * 32 + lane;
        float e = (k < K) ? expf(vals[t] - mx) : 0.f;
        vals[t] = e;
        sum += e;
    }
#pragma unroll
    for (int o = 16; o; o >>= 1) sum += __shfl_xor_sync(0xffffffffu, sum, o);
    float inv = 1.0f / sum;
    for (int t = 0; t < slots; t++) {
        int k = t * 32 + lane;
        if (k < ldout) Sout[(size_t)gw * ldout + k] = (k < K) ? vals[t] * inv : 0.f;
    }
}

// ---------------------------------------------------------------------------
__device__ __forceinline__ float blockReduce128(float v, float* sm) {
    int t = threadIdx.x;
    sm[t] = v;
    __syncthreads();
    for (int s = 64; s > 0; s >>= 1) {
        if (t < s) sm[t] += sm[t + s];
        __syncthreads();
    }
    float r = sm[0];
    __syncthreads();
    return r;
}

// losses + normalized pooled adjacency + its row-sums (next-level dflat)
__global__ void loss_norm_kernel(const float* __restrict__ raw,
                                 const float* __restrict__ ss,
                                 const float* __restrict__ s,
                                 const float* __restrict__ dflat,
                                 float* __restrict__ adjn,
                                 float* __restrict__ dflat2,
                                 float* __restrict__ lossb,
                                 int k, int n, int ld, int ld_s, int bstride) {
    int b = blockIdx.x;
    raw  += (size_t)b * bstride;
    ss   += (size_t)b * bstride;
    s    += (size_t)b * n * ld_s;
    dflat+= (size_t)b * n;
    adjn += (size_t)b * k * k;
    dflat2 += (size_t)b * k;
    __shared__ float sm[128];
    __shared__ float dc[128];
    __shared__ float idc[128];
    int tid = threadIdx.x;

    float v = 0.f;
    for (int i = tid; i < k; i += 128) v += raw[i * ld + i];
    float num = blockReduce128(v, sm);

    v = 0.f;
    for (int nn = tid; nn < n; nn += 128) {
        float dv = dflat[nn];
        float acc = 0.f;
        for (int kk = 0; kk < k; kk++) {
            float sv = s[(size_t)nn * ld_s + kk];
            acc += sv * sv;
        }
        v += acc * dv;
    }
    float den = blockReduce128(v, sm);

    v = 0.f;
    for (int i = tid; i < k; i += 128)
        for (int j = 0; j < k; j++) { float t = ss[i * ld + j]; v += t * t; }
    float nrm = sqrtf(blockReduce128(v, sm));

    float invn = 1.0f / nrm;
    float dk = rsqrtf((float)k);
    v = 0.f;
    for (int i = tid; i < k; i += 128)
        for (int j = 0; j < k; j++) {
            float t = ss[i * ld + j] * invn - ((i == j) ? dk : 0.f);
            v += t * t;
        }
    float ortho = sqrtf(blockReduce128(v, sm));

    for (int i = tid; i < k; i += 128) {
        float r = 0.f;
        for (int j = 0; j < k; j++) if (j != i) r += raw[i * ld + j];
        float d = sqrtf(r) + EPSV;
        dc[i] = d;
        idc[i] = 1.0f / d;
    }
    __syncthreads();
    for (int idx = tid; idx < k * k; idx += 128) {
        int i = idx / k, j = idx - i * k;
        adjn[idx] = (i == j) ? 0.f : raw[i * ld + j] * idc[i] * idc[j];
    }
    for (int i = tid; i < k; i += 128) {
        float r = 0.f;
        for (int j = 0; j < k; j++) if (j != i) r += raw[i * ld + j] * idc[j];
        dflat2[i] = r * idc[i];
    }
    if (tid == 0) lossb[b] += -num / den + ortho;
}

// ---------------------------------------------------------------------------
// stage2 conv: T2 = adj1@x1 (smem), x2 = relu(T2@relW + relb + x1@rootW),
// s2 = softmax(x2@p2W + p2b). One block per graph, 256 threads.
// ---------------------------------------------------------------------------
__global__ __launch_bounds__(256) void stage2_conv_kernel(
    const float* __restrict__ adj1, const float* __restrict__ x1,
    const float* __restrict__ relW, const float* __restrict__ relb,
    const float* __restrict__ rootW,
    const float* __restrict__ p2W, const float* __restrict__ p2b,
    float* __restrict__ x2, float* __restrict__ s2) {
    extern __shared__ float sm[];
    float* adj1s = sm;                       // 10000
    float* x1s   = sm + 10000;               // 3200
    float* relWs = sm + 13200;               // 1024
    float* rootWs= sm + 14224;               // 1024
    float* p2Ws  = sm + 15248;               // 320
    int b = blockIdx.x, tid = threadIdx.x;
    const float* A = adj1 + (size_t)b * KA * KA;
    const float* X = x1 + (size_t)b * KA * HID;
    for (int i = tid; i < KA * KA; i += 256) adj1s[i] = A[i];
    for (int i = tid; i < KA * HID; i += 256) x1s[i] = X[i];
    for (int i = tid; i < HID * HID; i += 256) { relWs[i] = relW[i]; rootWs[i] = rootW[i]; }
    for (int i = tid; i < HID * KB; i += 256) p2Ws[i] = p2W[i];
    __syncthreads();
    int lane = tid & 31, warp = tid >> 5;
    float rb = relb[lane];
    int kk10 = lane < KB ? lane : 0;
    float p2bv = p2b[kk10];
    for (int i = warp; i < KA; i += 8) {
        float t2 = 0.f;
        const float* ar = adj1s + i * KA;
        for (int m = 0; m < KA; m++) t2 += ar[m] * x1s[(m << 5) + lane];
        float x1v = x1s[(i << 5) + lane];
        float a = rb;
#pragma unroll
        for (int k = 0; k < 32; k++)
            a += __shfl_sync(0xffffffffu, t2, k) * relWs[(k << 5) + lane]
               + __shfl_sync(0xffffffffu, x1v, k) * rootWs[(k << 5) + lane];
        float x2v = fmaxf(a, 0.f);
        x2[((size_t)b * KA + i) * HID + lane] = x2v;
        // softmax over KB=10
        float zz = p2bv;
#pragma unroll
        for (int c = 0; c < 32; c++)
            zz += __shfl_sync(0xffffffffu, x2v, c) * p2Ws[c * KB + kk10];
        float z = (lane < KB) ? zz : -INFINITY;
        float mx = z;
#pragma unroll
        for (int o = 16; o; o >>= 1) mx = fmaxf(mx, __shfl_xor_sync(0xffffffffu, mx, o));
        float e = (lane < KB) ? expf(z - mx) : 0.f;
        float ssum = e;
#pragma unroll
        for (int o = 16; o; o >>= 1) ssum += __shfl_xor_sync(0xffffffffu, ssum, o);
        if (lane < KB) s2[((size_t)b * KA + i) * KB + lane] = e / ssum;
    }
}

// ---------------------------------------------------------------------------
// stage2b: TT2 = adj1@s2 (smem), adjr2 = s2^T TT2, ss2 = s2^T s2, x3 = s2^T x2
// ---------------------------------------------------------------------------
__global__ __launch_bounds__(256) void stage2b_kernel(
    const float* __restrict__ adj1, const float* __restrict__ s2,
    const float* __restrict__ x2,
    float* __restrict__ adjr2, float* __restrict__ ss2, float* __restrict__ x3) {
    extern __shared__ float sm[];
    float* adj1s = sm;             // 10000
    float* s2s   = sm + 10000;     // 1000
    float* x2s   = sm + 11000;     // 3200
    float* tt2s  = sm + 14200;     // 1000
    int b = blockIdx.x, tid = threadIdx.x;
    const float* A = adj1 + (size_t)b * KA * KA;
    const float* S2 = s2 + (size_t)b * KA * KB;
    const float* X2 = x2 + (size_t)b * KA * HID;
    for (int i = tid; i < KA * KA; i += 256) adj1s[i] = A[i];
    for (int i = tid; i < KA * KB; i += 256) s2s[i] = S2[i];
    for (int i = tid; i < KA * HID; i += 256) x2s[i] = X2[i];
    __syncthreads();
    for (int t = tid; t < KA * KB; t += 256) {
        int i = t / KB, k = t - i * KB;
        float a = 0.f;
        const float* ar = adj1s + i * KA;
        for (int m = 0; m < KA; m++) a += ar[m] * s2s[m * KB + k];
        tt2s[t] = a;
    }
    __syncthreads();
    for (int t = tid; t < 520; t += 256) {
        if (t < 100) {
            int i = t / 10, j = t - i * 10;
            float a = 0.f;
            for (int n = 0; n < KA; n++) a += s2s[n * KB + i] * tt2s[n * KB + j];
            adjr2[(size_t)b * 100 + t] = a;
        } else if (t < 200) {
            int u = t - 100;
            int i = u / 10, j = u - i * 10;
            float a = 0.f;
            for (int n = 0; n < KA; n++) a += s2s[n * KB + i] * s2s[n * KB + j];
            ss2[(size_t)b * 100 + u] = a;
        } else {
            int u = t - 200;          // u < 320: i = u>>5, c = u&31
            int i = u >> 5, c = u & 31;
            float a = 0.f;
            for (int n = 0; n < KA; n++) a += s2s[n * KB + i] * x2s[(n << 5) + c];
            x3[(size_t)b * 320 + u] = a;
        }
    }
}

// ---------------------------------------------------------------------------
// tail: t3 = adj2@x3, x4 = t3@c3rW + c3rb + x3@c3oW, mean -> lin1 relu -> lin2
// -> log_softmax. One 32-thread block per graph.
// ---------------------------------------------------------------------------
__global__ void tail_kernel(const float* __restrict__ adj2, const float* __restrict__ x3,
                            const float* __restrict__ c3rW, const float* __restrict__ c3rb,
                            const float* __restrict__ c3oW,
                            const float* __restrict__ l1W, const float* __restrict__ l1b,
                            const float* __restrict__ l2W, const float* __restrict__ l2b,
                            float* __restrict__ out) {
    int b = blockIdx.x, lane = threadIdx.x;
    const float* A2 = adj2 + (size_t)b * 100;
    const float* X3 = x3 + (size_t)b * 320;
    float x3c[10], t3c[10];
#pragma unroll
    for (int j = 0; j < 10; j++) x3c[j] = X3[j * 32 + lane];
#pragma unroll
    for (int i = 0; i < 10; i++) {
        float a = 0.f;
#pragma unroll
        for (int j = 0; j < 10; j++) a += A2[i * 10 + j] * x3c[j];
        t3c[i] = a;
    }
    float rb = c3rb[lane];
    float g = 0.f;
#pragma unroll
    for (int i = 0; i < 10; i++) {
        float a = rb;
#pragma unroll
        for (int k = 0; k < 32; k++)
            a += __shfl_sync(0xffffffffu, t3c[i], k) * c3rW[k * 32 + lane]
               + __shfl_sync(0xffffffffu, x3c[i], k) * c3oW[k * 32 + lane];
        g += a;
    }
    g *= 0.1f;
    float a1 = l1b[lane];
#pragma unroll
    for (int k = 0; k < 32; k++) a1 += __shfl_sync(0xffffffffu, g, k) * l1W[k * 32 + lane];
    float gg = fmaxf(a1, 0.f);
    int kk = lane < OC ? lane : 0;
    float a2 = l2b[kk];
#pragma unroll
    for (int k = 0; k < 32; k++) a2 += __shfl_sync(0xffffffffu, gg, k) * l2W[k * OC + kk];
    float val = (lane < OC) ? a2 : -INFINITY;
    float m = val;
#pragma unroll
    for (int o = 16; o; o >>= 1) m = fmaxf(m, __shfl_xor_sync(0xffffffffu, m, o));
    float e = (lane < OC) ? expf(val - m) : 0.f;
    float ssum = e;
#pragma unroll
    for (int o = 16; o; o >>= 1) ssum += __shfl_xor_sync(0xffffffffu, ssum, o);
    if (lane < OC) out[b * OC + lane] = val - m - logf(ssum);
}

__global__ void final_kernel(const float* __restrict__ lossb, float* __restrict__ out,
                             int out_size) {
    __shared__ float sm[128];
    int t = threadIdx.x;
    sm[t] = lossb[t];
    __syncthreads();
    for (int s = 64; s > 0; s >>= 1) {
        if (t < s) sm[t] += sm[t + s];
        __syncthreads();
    }
    if (t == 0 && out_size > BATCH * OC) out[BATCH * OC] = sm[0] / (float)BATCH;
}

// ---------------------------------------------------------------------------
extern "C" void kernel_launch(void* const* d_in, const int* in_sizes, int n_in,
                              void* d_out, int out_size) {
    const float* x    = (const float*)d_in[0];
    const int*   ei   = (const int*)  d_in[1];
    const float* c1W  = (const float*)d_in[3];
    const float* c1b  = (const float*)d_in[4];
    const float* p1W  = (const float*)d_in[5];
    const float* p1b  = (const float*)d_in[6];
    const float* c2rW = (const float*)d_in[7];
    const float* c2rb = (const float*)d_in[8];
    const float* c2oW = (const float*)d_in[9];
    const float* p2W  = (const float*)d_in[10];
    const float* p2b  = (const float*)d_in[11];
    const float* c3rW = (const float*)d_in[12];
    const float* c3rb = (const float*)d_in[13];
    const float* c3oW = (const float*)d_in[14];
    const float* l1W  = (const float*)d_in[15];
    const float* l1b  = (const float*)d_in[16];
    const float* l2W  = (const float*)d_in[17];
    const float* l2b  = (const float*)d_in[18];
    float* out = (float*)d_out;
    int E = in_sizes[1] / 2;
    int eper = E / BATCH;

    void* sp = nullptr;
    cudaGetSymbolAddress(&sp, g_scratch);
    float* S = (float*)sp;

    cudaFuncSetAttribute(agg_sparse_kernel, cudaFuncAttributeMaxDynamicSharedMemorySize, 65536);
    cudaFuncSetAttribute(t1_sparse_kernel, cudaFuncAttributeMaxDynamicSharedMemorySize, 65536);
    cudaFuncSetAttribute(stage2_conv_kernel, cudaFuncAttributeMaxDynamicSharedMemorySize, 62272);
    cudaFuncSetAttribute(stage2b_kernel, cudaFuncAttributeMaxDynamicSharedMemorySize, 60800);

    zero_kernel<<<256, 256>>>((float4*)S, ZERO_CNT / 4);
    scatter_kernel<<<(E + 255) / 256, 256>>>(ei, E, S + OFF_DEG, S + OFF_DFLAT);
    xwp_kernel<<<TOT / 8, dim3(32, 8)>>>(x, c1W, S + OFF_DEG, S + OFF_XWP);
    agg_sparse_kernel<<<BATCH, 512, 65536>>>(ei, E, eper, S + OFF_XWP, S + OFF_DEG, c1b, S + OFF_H);
    pool_softmax<<<TOT * 32 / 256, 256>>>(S + OFF_H, p1W, p1b, S + OFF_S1, TOT, KA, KAP);
    { dim3 g(4, BATCH); t1_sparse_kernel<<<g, 512, 65536>>>(ei, E, eper, S + OFF_S1, S + OFF_T1); }
    { dim3 g(2, BATCH); atb8_128_kernel<<<g, 256>>>(S + OFF_S1, S + OFF_T1, S + OFF_ADJR1, S + OFF_SS1); }
    atb8_32_kernel<<<BATCH, 256>>>(S + OFF_S1, S + OFF_H, S + OFF_X1);
    loss_norm_kernel<<<BATCH, 128>>>(S + OFF_ADJR1, S + OFF_SS1, S + OFF_S1, S + OFF_DFLAT,
                                     S + OFF_ADJ1, S + OFF_DFLAT2, S + OFF_LOSSB,
                                     KA, NNODE, KAP, KAP, KAP * KAP);
    stage2_conv_kernel<<<BATCH, 256, 62272>>>(S + OFF_ADJ1, S + OFF_X1, c2rW, c2rb, c2oW,
                                              p2W, p2b, S + OFF_X2, S + OFF_S2);
    stage2b_kernel<<<BATCH, 256, 60800>>>(S + OFF_ADJ1, S + OFF_S2, S + OFF_X2,
                                          S + OFF_ADJR2, S + OFF_SS2, S + OFF_X3);
    loss_norm_kernel<<<BATCH, 128>>>(S + OFF_ADJR2, S + OFF_SS2, S + OFF_S2, S + OFF_DFLAT2,
                                     S + OFF_ADJ2, S + OFF_DUMMY, S + OFF_LOSSB,
                                     KB, KA, KB, KB, KB * KB);
    tail_kernel<<<BATCH, 32>>>(S + OFF_ADJ2, S + OFF_X3, c3rW, c3rb, c3oW,
                               l1W, l1b, l2W, l2b, out);
    final_kernel<<<1, 128>>>(S + OFF_LOSSB, out, out_size);
}

// round 4
// speedup vs baseline: 2.4058x; 1.4747x over previous
#include <cuda_runtime.h>
#include <math.h>

namespace {
constexpr int BATCH = 128, NNODE = 512, INC = 128, HID = 32, KA = 100, KB = 10, OC = 10;
constexpr int KAP = 128;
constexpr int TOT = BATCH * NNODE;
constexpr int MAXE = BATCH * 8192;
constexpr float EPSV = 1e-15f;

constexpr size_t OFF_DEG    = 0;
constexpr size_t OFF_DFLAT  = OFF_DEG + TOT;
constexpr size_t OFF_LOSSB  = OFF_DFLAT + TOT;
constexpr size_t OFF_XWP    = OFF_LOSSB + BATCH;
constexpr size_t OFF_H      = OFF_XWP   + (size_t)TOT * HID;
constexpr size_t OFF_S1     = OFF_H     + (size_t)TOT * HID;
constexpr size_t OFF_T1     = OFF_S1    + (size_t)TOT * KAP;
constexpr size_t OFF_ADJR1  = OFF_T1    + (size_t)TOT * KAP;
constexpr size_t OFF_SS1    = OFF_ADJR1 + (size_t)BATCH * KAP * KAP;
constexpr size_t OFF_X1     = OFF_SS1   + (size_t)BATCH * KAP * KAP;
constexpr size_t OFF_ADJ1   = OFF_X1    + (size_t)BATCH * KA * HID;
constexpr size_t OFF_DFLAT2 = OFF_ADJ1  + (size_t)BATCH * KA * KA;
constexpr size_t OFF_DUMMY  = OFF_DFLAT2+ (size_t)BATCH * KA;
constexpr size_t OFF_X2     = OFF_DUMMY + (size_t)BATCH * KB;
constexpr size_t OFF_S2     = OFF_X2    + (size_t)BATCH * KA * HID;
constexpr size_t OFF_ADJR2  = OFF_S2    + (size_t)BATCH * KA * KB;
constexpr size_t OFF_SS2    = OFF_ADJR2 + (size_t)BATCH * KB * KB;
constexpr size_t OFF_X3     = OFF_SS2   + (size_t)BATCH * KB * KB;
constexpr size_t OFF_ADJ2   = OFF_X3    + (size_t)BATCH * KB * HID;
constexpr size_t SCRATCH_TOTAL = OFF_ADJ2 + (size_t)BATCH * KB * KB;
}  // namespace

__device__ __align__(16) float g_scratch[SCRATCH_TOTAL];
__device__ __align__(16) int g_cnt_src[TOT];
__device__ __align__(16) int g_cnt_dst[TOT];
__device__ __align__(16) int g_off_src[TOT];
__device__ __align__(16) int g_off_dst[TOT];
__device__ __align__(16) int g_cur_src[TOT];
__device__ __align__(16) int g_cur_dst[TOT];
__device__ __align__(16) int g_list_src[MAXE];   // dst-locals grouped by src
__device__ __align__(16) int g_list_dst[MAXE];   // src-locals grouped by dst

// ---------------------------------------------------------------------------
// zero: per-run state (counts + per-graph loss)
// ---------------------------------------------------------------------------
__global__ void zero_state_kernel(int* cs, int* cd, float* lossb) {
    int i = blockIdx.x * blockDim.x + threadIdx.x;
    if (i < TOT) { cs[i] = 0; cd[i] = 0; }
    if (i < BATCH) lossb[i] = 0.f;
}

__global__ void count_kernel(const int* __restrict__ ei, int E,
                             int* __restrict__ cs, int* __restrict__ cd) {
    int e = blockIdx.x * blockDim.x + threadIdx.x;
    if (e >= E) return;
    atomicAdd(&cs[ei[e]], 1);
    atomicAdd(&cd[ei[E + e]], 1);
}

// per-graph exclusive scans of out/in counts -> CSR offsets (+cursors), float degs
__global__ __launch_bounds__(512) void scan_kernel(
    const int* __restrict__ cs, const int* __restrict__ cd, int eper,
    int* __restrict__ off_src, int* __restrict__ cur_src,
    int* __restrict__ off_dst, int* __restrict__ cur_dst,
    float* __restrict__ deg, float* __restrict__ dflat) {
    __shared__ int sh[512];
    int b = blockIdx.x, tid = threadIdx.x;
    int g = (b << 9) + tid;
    int base = b * eper;
    int vs = cs[g], vd = cd[g];
    dflat[g] = (float)vs;
    deg[g]   = (float)vd;
    sh[tid] = vs; __syncthreads();
    for (int o = 1; o < 512; o <<= 1) {
        int t = (tid >= o) ? sh[tid - o] : 0;
        __syncthreads(); sh[tid] += t; __syncthreads();
    }
    int es = sh[tid] - vs;
    off_src[g] = base + es; cur_src[g] = base + es;
    __syncthreads();
    sh[tid] = vd; __syncthreads();
    for (int o = 1; o < 512; o <<= 1) {
        int t = (tid >= o) ? sh[tid - o] : 0;
        __syncthreads(); sh[tid] += t; __syncthreads();
    }
    int ed = sh[tid] - vd;
    off_dst[g] = base + ed; cur_dst[g] = base + ed;
}

__global__ void fill_kernel(const int* __restrict__ ei, int E,
                            int* __restrict__ cur_src, int* __restrict__ cur_dst,
                            int* __restrict__ list_src, int* __restrict__ list_dst) {
    int e = blockIdx.x * blockDim.x + threadIdx.x;
    if (e >= E) return;
    int s = ei[e], d = ei[E + e];
    int p = atomicAdd(&cur_src[s], 1);
    list_src[p] = d & 511;
    int q = atomicAdd(&cur_dst[d], 1);
    list_dst[q] = s & 511;
}

// ---------------------------------------------------------------------------
// xwp[g][c] = rsqrt(deg[g]+1) * (x @ conv1_W)[g][c]
// ---------------------------------------------------------------------------
__global__ __launch_bounds__(256) void xwp_kernel(const float* __restrict__ x,
                                                  const float* __restrict__ W,
                                                  const float* __restrict__ deg,
                                                  float* __restrict__ xwp) {
    __shared__ float Ws[INC * HID];
    __shared__ float xs[8][INC];
    int tid = threadIdx.y * 32 + threadIdx.x;
    for (int t = tid; t < INC * HID; t += 256) Ws[t] = W[t];
    int r0 = blockIdx.x * 8;
    for (int t = tid; t < 8 * INC; t += 256) {
        int r = t >> 7, k = t & 127;
        xs[r][k] = x[(size_t)(r0 + r) * INC + k];
    }
    __syncthreads();
    int c = threadIdx.x, r = threadIdx.y;
    float acc = 0.f;
#pragma unroll 8
    for (int k = 0; k < INC; k++) acc += xs[r][k] * Ws[k * HID + c];
    int g = r0 + r;
    float dis = rsqrtf(deg[g] + 1.0f);
    xwp[(size_t)g * HID + c] = dis * acc;
}

// ---------------------------------------------------------------------------
// GCN aggregate via gather: one warp per dest node; lane = column.
// h[d][c] = relu( dis_d * ( sum_{s in in(d)} xwp[s][c] + xwp[d][c] ) + bias[c] )
// ---------------------------------------------------------------------------
__global__ __launch_bounds__(256) void agg_gather_kernel(
    const int* __restrict__ off_dst, const int* __restrict__ cnt_dst,
    const int* __restrict__ list_dst,
    const float* __restrict__ xwp, const float* __restrict__ deg,
    const float* __restrict__ bias, float* __restrict__ h) {
    int node = (blockIdx.x * blockDim.x + threadIdx.x) >> 5;
    int lane = threadIdx.x & 31;
    if (node >= TOT) return;
    int b = node >> 9;
    const float* xb = xwp + (((size_t)b << 9) << 5);
    int off = off_dst[node], cnt = cnt_dst[node];
    float acc = 0.f;
    int i = off;
    for (; i + 1 < off + cnt; i += 2) {
        int s0 = list_dst[i], s1 = list_dst[i + 1];
        acc += xb[(s0 << 5) + lane] + xb[(s1 << 5) + lane];
    }
    if (i < off + cnt) acc += xb[(list_dst[i] << 5) + lane];
    float dis = rsqrtf(deg[node] + 1.0f);
    float xv = xwp[((size_t)node << 5) + lane];
    h[((size_t)node << 5) + lane] = fmaxf(dis * (acc + xv) + bias[lane], 0.f);
}

// ---------------------------------------------------------------------------
// T1 = A @ s1 via gather: one warp per source node; lane = float4 column chunk.
// T1[s][0:128] = sum_{d in out(s)} s1[d][0:128]
// ---------------------------------------------------------------------------
__global__ __launch_bounds__(256) void t1_gather_kernel(
    const int* __restrict__ off_src, const int* __restrict__ cnt_src,
    const int* __restrict__ list_src,
    const float* __restrict__ s1p, float* __restrict__ T1) {
    int node = (blockIdx.x * blockDim.x + threadIdx.x) >> 5;
    int lane = threadIdx.x & 31;
    if (node >= TOT) return;
    int b = node >> 9;
    const float4* sb = (const float4*)(s1p + (((size_t)b << 9) << 7)) + lane;
    int off = off_src[node], cnt = cnt_src[node];
    float4 acc = make_float4(0, 0, 0, 0);
    int i = off;
    for (; i + 1 < off + cnt; i += 2) {
        int d0 = list_src[i], d1 = list_src[i + 1];
        float4 v0 = sb[d0 << 5];
        float4 v1 = sb[d1 << 5];
        acc.x += v0.x + v1.x; acc.y += v0.y + v1.y;
        acc.z += v0.z + v1.z; acc.w += v0.w + v1.w;
    }
    if (i < off + cnt) {
        float4 v = sb[list_src[i] << 5];
        acc.x += v.x; acc.y += v.y; acc.z += v.z; acc.w += v.w;
    }
    ((float4*)(T1 + ((size_t)node << 7)))[lane] = acc;
}

// ---------------------------------------------------------------------------
// adjr1 = s1^T T1, ss1 = s1^T s1 (128x128 padded, K=512). micro 8x8.
// ---------------------------------------------------------------------------
__global__ __launch_bounds__(256) void atb8_128_kernel(const float* __restrict__ s1p,
                                                       const float* __restrict__ T1,
                                                       float* __restrict__ adjr1,
                                                       float* __restrict__ ss1) {
    __shared__ float As[16][128];
    __shared__ float Bs[16][128];
    int b = blockIdx.y;
    int sel = blockIdx.x;
    const float* A = s1p + ((size_t)b << 9) * KAP;
    const float* B = (sel ? s1p : T1) + ((size_t)b << 9) * KAP;
    float* C = (sel ? ss1 : adjr1) + (size_t)b * KAP * KAP;
    int tid = threadIdx.x;
    int tx = tid & 15, ty = tid >> 4;
    float acc[8][8] = {};
    for (int n0 = 0; n0 < NNODE; n0 += 16) {
#pragma unroll
        for (int r = 0; r < 2; r++) {
            int t4 = tid + r * 256;
            int kk = t4 >> 5, jf = (t4 & 31) << 2;
            *(float4*)&As[kk][jf] = *(const float4*)(A + (n0 + kk) * KAP + jf);
            *(float4*)&Bs[kk][jf] = *(const float4*)(B + (n0 + kk) * KAP + jf);
        }
        __syncthreads();
#pragma unroll
        for (int kk = 0; kk < 16; kk++) {
            float4 a0 = *(float4*)&As[kk][ty * 8];
            float4 a1 = *(float4*)&As[kk][ty * 8 + 4];
            float4 b0 = *(float4*)&Bs[kk][tx * 8];
            float4 b1 = *(float4*)&Bs[kk][tx * 8 + 4];
            float a[8] = {a0.x, a0.y, a0.z, a0.w, a1.x, a1.y, a1.z, a1.w};
            float bv[8] = {b0.x, b0.y, b0.z, b0.w, b1.x, b1.y, b1.z, b1.w};
#pragma unroll
            for (int u = 0; u < 8; u++)
#pragma unroll
                for (int v = 0; v < 8; v++) acc[u][v] += a[u] * bv[v];
        }
        __syncthreads();
    }
#pragma unroll
    for (int u = 0; u < 8; u++) {
        int row = ty * 8 + u;
        *(float4*)&C[(size_t)row * KAP + tx * 8] =
            make_float4(acc[u][0], acc[u][1], acc[u][2], acc[u][3]);
        *(float4*)&C[(size_t)row * KAP + tx * 8 + 4] =
            make_float4(acc[u][4], acc[u][5], acc[u][6], acc[u][7]);
    }
}

// ---------------------------------------------------------------------------
// x1 = s1^T h  (I=128 pad -> write <100, J=32, K=512)
// ---------------------------------------------------------------------------
__global__ __launch_bounds__(256) void atb8_32_kernel(const float* __restrict__ s1p,
                                                      const float* __restrict__ h,
                                                      float* __restrict__ x1) {
    __shared__ float As[16][128];
    __shared__ float Bs[16][32];
    int b = blockIdx.x;
    const float* A = s1p + ((size_t)b << 9) * KAP;
    const float* B = h + ((size_t)b << 9) * HID;
    float* C = x1 + (size_t)b * KA * HID;
    int tid = threadIdx.x;
    int tx = tid & 7, ty = tid >> 3;
    float acc[4][4] = {};
    for (int n0 = 0; n0 < NNODE; n0 += 16) {
#pragma unroll
        for (int r = 0; r < 2; r++) {
            int t4 = tid + r * 256;
            int kk = t4 >> 5, jf = (t4 & 31) << 2;
            *(float4*)&As[kk][jf] = *(const float4*)(A + (n0 + kk) * KAP + jf);
        }
        if (tid < 128) {
            int kk = tid >> 3, jf = (tid & 7) << 2;
            *(float4*)&Bs[kk][jf] = *(const float4*)(B + (n0 + kk) * HID + jf);
        }
        __syncthreads();
#pragma unroll
        for (int kk = 0; kk < 16; kk++) {
            float4 av = *(float4*)&As[kk][ty * 4];
            float4 bb = *(float4*)&Bs[kk][tx * 4];
            float a[4] = {av.x, av.y, av.z, av.w};
            float bv[4] = {bb.x, bb.y, bb.z, bb.w};
#pragma unroll
            for (int u = 0; u < 4; u++)
#pragma unroll
                for (int v = 0; v < 4; v++) acc[u][v] += a[u] * bv[v];
        }
        __syncthreads();
    }
#pragma unroll
    for (int u = 0; u < 4; u++) {
        int row = ty * 4 + u;
        if (row < KA)
            *(float4*)&C[(size_t)row * HID + tx * 4] =
                make_float4(acc[u][0], acc[u][1], acc[u][2], acc[u][3]);
    }
}

// ---------------------------------------------------------------------------
// S = softmax(X @ W + b), padded output ld (zeros in pad cols)
// ---------------------------------------------------------------------------
__global__ void pool_softmax(const float* __restrict__ X, const float* __restrict__ W,
                             const float* __restrict__ bias, float* __restrict__ Sout,
                             int rows, int K, int ldout) {
    int gw = (blockIdx.x * blockDim.x + threadIdx.x) >> 5;
    int lane = threadIdx.x & 31;
    if (gw >= rows) return;
    float xv = X[(size_t)gw * HID + lane];
    int slots = (ldout + 31) >> 5;
    float vals[4];
    float mx = -INFINITY;
    for (int t = 0; t < slots; t++) {
        int k = t * 32 + lane;
        float acc = 0.f;
#pragma unroll
        for (int c = 0; c < HID; c++) {
            float w = (k < K) ? W[c * K + k] : 0.f;
            acc += __shfl_sync(0xffffffffu, xv, c) * w;
        }
        float v = (k < K) ? acc + bias[k] : -INFINITY;
        vals[t] = v;
        mx = fmaxf(mx, v);
    }
#pragma unroll
    for (int o = 16; o; o >>= 1) mx = fmaxf(mx, __shfl_xor_sync(0xffffffffu, mx, o));
    float sum = 0.f;
    for (int t = 0; t < slots; t++) {
        int k = t * 32 + lane;
        float e = (k < K) ? expf(vals[t] - mx) : 0.f;
        vals[t] = e;
        sum += e;
    }
#pragma unroll
    for (int o = 16; o; o >>= 1) sum += __shfl_xor_sync(0xffffffffu, sum, o);
    float inv = 1.0f / sum;
    for (int t = 0; t < slots; t++) {
        int k = t * 32 + lane;
        if (k < ldout) Sout[(size_t)gw * ldout + k] = (k < K) ? vals[t] * inv : 0.f;
    }
}

// ---------------------------------------------------------------------------
__device__ __forceinline__ float blockReduce128(float v, float* sm) {
    int t = threadIdx.x;
    sm[t] = v;
    __syncthreads();
    for (int s = 64; s > 0; s >>= 1) {
        if (t < s) sm[t] += sm[t + s];
        __syncthreads();
    }
    float r = sm[0];
    __syncthreads();
    return r;
}

__global__ void loss_norm_kernel(const float* __restrict__ raw,
                                 const float* __restrict__ ss,
                                 const float* __restrict__ s,
                                 const float* __restrict__ dflat,
                                 float* __restrict__ adjn,
                                 float* __restrict__ dflat2,
                                 float* __restrict__ lossb,
                                 int k, int n, int ld, int ld_s, int bstride) {
    int b = blockIdx.x;
    raw  += (size_t)b * bstride;
    ss   += (size_t)b * bstride;
    s    += (size_t)b * n * ld_s;
    dflat+= (size_t)b * n;
    adjn += (size_t)b * k * k;
    dflat2 += (size_t)b * k;
    __shared__ float sm[128];
    __shared__ float idc[128];
    int tid = threadIdx.x;

    float v = 0.f;
    for (int i = tid; i < k; i += 128) v += raw[i * ld + i];
    float num = blockReduce128(v, sm);

    v = 0.f;
    for (int nn = tid; nn < n; nn += 128) {
        float dv = dflat[nn];
        float acc = 0.f;
        for (int kk = 0; kk < k; kk++) {
            float sv = s[(size_t)nn * ld_s + kk];
            acc += sv * sv;
        }
        v += acc * dv;
    }
    float den = blockReduce128(v, sm);

    v = 0.f;
    for (int i = tid; i < k; i += 128)
        for (int j = 0; j < k; j++) { float t = ss[i * ld + j]; v += t * t; }
    float nrm = sqrtf(blockReduce128(v, sm));

    float invn = 1.0f / nrm;
    float dk = rsqrtf((float)k);
    v = 0.f;
    for (int i = tid; i < k; i += 128)
        for (int j = 0; j < k; j++) {
            float t = ss[i * ld + j] * invn - ((i == j) ? dk : 0.f);
            v += t * t;
        }
    float ortho = sqrtf(blockReduce128(v, sm));

    for (int i = tid; i < k; i += 128) {
        float r = 0.f;
        for (int j = 0; j < k; j++) if (j != i) r += raw[i * ld + j];
        idc[i] = 1.0f / (sqrtf(r) + EPSV);
    }
    __syncthreads();
    for (int idx = tid; idx < k * k; idx += 128) {
        int i = idx / k, j = idx - i * k;
        adjn[idx] = (i == j) ? 0.f : raw[i * ld + j] * idc[i] * idc[j];
    }
    for (int i = tid; i < k; i += 128) {
        float r = 0.f;
        for (int j = 0; j < k; j++) if (j != i) r += raw[i * ld + j] * idc[j];
        dflat2[i] = r * idc[i];
    }
    if (tid == 0) lossb[b] += -num / den + ortho;
}

// ---------------------------------------------------------------------------
__global__ __launch_bounds__(256) void stage2_conv_kernel(
    const float* __restrict__ adj1, const float* __restrict__ x1,
    const float* __restrict__ relW, const float* __restrict__ relb,
    const float* __restrict__ rootW,
    const float* __restrict__ p2W, const float* __restrict__ p2b,
    float* __restrict__ x2, float* __restrict__ s2) {
    extern __shared__ float sm[];
    float* adj1s = sm;
    float* x1s   = sm + 10000;
    float* relWs = sm + 13200;
    float* rootWs= sm + 14224;
    float* p2Ws  = sm + 15248;
    int b = blockIdx.x, tid = threadIdx.x;
    const float* A = adj1 + (size_t)b * KA * KA;
    const float* X = x1 + (size_t)b * KA * HID;
    for (int i = tid; i < KA * KA; i += 256) adj1s[i] = A[i];
    for (int i = tid; i < KA * HID; i += 256) x1s[i] = X[i];
    for (int i = tid; i < HID * HID; i += 256) { relWs[i] = relW[i]; rootWs[i] = rootW[i]; }
    for (int i = tid; i < HID * KB; i += 256) p2Ws[i] = p2W[i];
    __syncthreads();
    int lane = tid & 31, warp = tid >> 5;
    float rb = relb[lane];
    int kk10 = lane < KB ? lane : 0;
    float p2bv = p2b[kk10];
    for (int i = warp; i < KA; i += 8) {
        float t2 = 0.f;
        const float* ar = adj1s + i * KA;
        for (int m = 0; m < KA; m++) t2 += ar[m] * x1s[(m << 5) + lane];
        float x1v = x1s[(i << 5) + lane];
        float a = rb;
#pragma unroll
        for (int k = 0; k < 32; k++)
            a += __shfl_sync(0xffffffffu, t2, k) * relWs[(k << 5) + lane]
               + __shfl_sync(0xffffffffu, x1v, k) * rootWs[(k << 5) + lane];
        float x2v = fmaxf(a, 0.f);
        x2[((size_t)b * KA + i) * HID + lane] = x2v;
        float zz = p2bv;
#pragma unroll
        for (int c = 0; c < 32; c++)
            zz += __shfl_sync(0xffffffffu, x2v, c) * p2Ws[c * KB + kk10];
        float z = (lane < KB) ? zz : -INFINITY;
        float mx = z;
#pragma unroll
        for (int o = 16; o; o >>= 1) mx = fmaxf(mx, __shfl_xor_sync(0xffffffffu, mx, o));
        float e = (lane < KB) ? expf(z - mx) : 0.f;
        float ssum = e;
#pragma unroll
        for (int o = 16; o; o >>= 1) ssum += __shfl_xor_sync(0xffffffffu, ssum, o);
        if (lane < KB) s2[((size_t)b * KA + i) * KB + lane] = e / ssum;
    }
}

// ---------------------------------------------------------------------------
__global__ __launch_bounds__(256) void stage2b_kernel(
    const float* __restrict__ adj1, const float* __restrict__ s2,
    const float* __restrict__ x2,
    float* __restrict__ adjr2, float* __restrict__ ss2, float* __restrict__ x3) {
    extern __shared__ float sm[];
    float* adj1s = sm;
    float* s2s   = sm + 10000;
    float* x2s   = sm + 11000;
    float* tt2s  = sm + 14200;
    int b = blockIdx.x, tid = threadIdx.x;
    const float* A = adj1 + (size_t)b * KA * KA;
    const float* S2 = s2 + (size_t)b * KA * KB;
    const float* X2 = x2 + (size_t)b * KA * HID;
    for (int i = tid; i < KA * KA; i += 256) adj1s[i] = A[i];
    for (int i = tid; i < KA * KB; i += 256) s2s[i] = S2[i];
    for (int i = tid; i < KA * HID; i += 256) x2s[i] = X2[i];
    __syncthreads();
    for (int t = tid; t < KA * KB; t += 256) {
        int i = t / KB, k = t - i * KB;
        float a = 0.f;
        const float* ar = adj1s + i * KA;
        for (int m = 0; m < KA; m++) a += ar[m] * s2s[m * KB + k];
        tt2s[t] = a;
    }
    __syncthreads();
    for (int t = tid; t < 520; t += 256) {
        if (t < 100) {
            int i = t / 10, j = t - i * 10;
            float a = 0.f;
            for (int n = 0; n < KA; n++) a += s2s[n * KB + i] * tt2s[n * KB + j];
            adjr2[(size_t)b * 100 + t] = a;
        } else if (t < 200) {
            int u = t - 100;
            int i = u / 10, j = u - i * 10;
            float a = 0.f;
            for (int n = 0; n < KA; n++) a += s2s[n * KB + i] * s2s[n * KB + j];
            ss2[(size_t)b * 100 + u] = a;
        } else {
            int u = t - 200;
            int i = u >> 5, c = u & 31;
            float a = 0.f;
            for (int n = 0; n < KA; n++) a += s2s[n * KB + i] * x2s[(n << 5) + c];
            x3[(size_t)b * 320 + u] = a;
        }
    }
}

// ---------------------------------------------------------------------------
__global__ void tail_kernel(const float* __restrict__ adj2, const float* __restrict__ x3,
                            const float* __restrict__ c3rW, const float* __restrict__ c3rb,
                            const float* __restrict__ c3oW,
                            const float* __restrict__ l1W, const float* __restrict__ l1b,
                            const float* __restrict__ l2W, const float* __restrict__ l2b,
                            float* __restrict__ out) {
    int b = blockIdx.x, lane = threadIdx.x;
    const float* A2 = adj2 + (size_t)b * 100;
    const float* X3 = x3 + (size_t)b * 320;
    float x3c[10], t3c[10];
#pragma unroll
    for (int j = 0; j < 10; j++) x3c[j] = X3[j * 32 + lane];
#pragma unroll
    for (int i = 0; i < 10; i++) {
        float a = 0.f;
#pragma unroll
        for (int j = 0; j < 10; j++) a += A2[i * 10 + j] * x3c[j];
        t3c[i] = a;
    }
    float rb = c3rb[lane];
    float g = 0.f;
#pragma unroll
    for (int i = 0; i < 10; i++) {
        float a = rb;
#pragma unroll
        for (int k = 0; k < 32; k++)
            a += __shfl_sync(0xffffffffu, t3c[i], k) * c3rW[k * 32 + lane]
               + __shfl_sync(0xffffffffu, x3c[i], k) * c3oW[k * 32 + lane];
        g += a;
    }
    g *= 0.1f;
    float a1 = l1b[lane];
#pragma unroll
    for (int k = 0; k < 32; k++) a1 += __shfl_sync(0xffffffffu, g, k) * l1W[k * 32 + lane];
    float gg = fmaxf(a1, 0.f);
    int kk = lane < OC ? lane : 0;
    float a2 = l2b[kk];
#pragma unroll
    for (int k = 0; k < 32; k++) a2 += __shfl_sync(0xffffffffu, gg, k) * l2W[k * OC + kk];
    float val = (lane < OC) ? a2 : -INFINITY;
    float m = val;
#pragma unroll
    for (int o = 16; o; o >>= 1) m = fmaxf(m, __shfl_xor_sync(0xffffffffu, m, o));
    float e = (lane < OC) ? expf(val - m) : 0.f;
    float ssum = e;
#pragma unroll
    for (int o = 16; o; o >>= 1) ssum += __shfl_xor_sync(0xffffffffu, ssum, o);
    if (lane < OC) out[b * OC + lane] = val - m - logf(ssum);
}

__global__ void final_kernel(const float* __restrict__ lossb, float* __restrict__ out,
                             int out_size) {
    __shared__ float sm[128];
    int t = threadIdx.x;
    sm[t] = lossb[t];
    __syncthreads();
    for (int s = 64; s > 0; s >>= 1) {
        if (t < s) sm[t] += sm[t + s];
        __syncthreads();
    }
    if (t == 0 && out_size > BATCH * OC) out[BATCH * OC] = sm[0] / (float)BATCH;
}

// ---------------------------------------------------------------------------
extern "C" void kernel_launch(void* const* d_in, const int* in_sizes, int n_in,
                              void* d_out, int out_size) {
    const float* x    = (const float*)d_in[0];
    const int*   ei   = (const int*)  d_in[1];
    const float* c1W  = (const float*)d_in[3];
    const float* c1b  = (const float*)d_in[4];
    const float* p1W  = (const float*)d_in[5];
    const float* p1b  = (const float*)d_in[6];
    const float* c2rW = (const float*)d_in[7];
    const float* c2rb = (const float*)d_in[8];
    const float* c2oW = (const float*)d_in[9];
    const float* p2W  = (const float*)d_in[10];
    const float* p2b  = (const float*)d_in[11];
    const float* c3rW = (const float*)d_in[12];
    const float* c3rb = (const float*)d_in[13];
    const float* c3oW = (const float*)d_in[14];
    const float* l1W  = (const float*)d_in[15];
    const float* l1b  = (const float*)d_in[16];
    const float* l2W  = (const float*)d_in[17];
    const float* l2b  = (const float*)d_in[18];
    float* out = (float*)d_out;
    int E = in_sizes[1] / 2;
    int eper = E / BATCH;

    void* sp = nullptr;
    cudaGetSymbolAddress(&sp, g_scratch);
    float* S = (float*)sp;
    int *csn, *cdn, *osn, *odn, *curs, *curd, *lsrc, *ldst;
    cudaGetSymbolAddress((void**)&csn, g_cnt_src);
    cudaGetSymbolAddress((void**)&cdn, g_cnt_dst);
    cudaGetSymbolAddress((void**)&osn, g_off_src);
    cudaGetSymbolAddress((void**)&odn, g_off_dst);
    cudaGetSymbolAddress((void**)&curs, g_cur_src);
    cudaGetSymbolAddress((void**)&curd, g_cur_dst);
    cudaGetSymbolAddress((void**)&lsrc, g_list_src);
    cudaGetSymbolAddress((void**)&ldst, g_list_dst);

    cudaFuncSetAttribute(stage2_conv_kernel, cudaFuncAttributeMaxDynamicSharedMemorySize, 62272);
    cudaFuncSetAttribute(stage2b_kernel, cudaFuncAttributeMaxDynamicSharedMemorySize, 60800);

    zero_state_kernel<<<(TOT + 255) / 256, 256>>>(csn, cdn, S + OFF_LOSSB);
    count_kernel<<<(E + 255) / 256, 256>>>(ei, E, csn, cdn);
    scan_kernel<<<BATCH, 512>>>(csn, cdn, eper, osn, curs, odn, curd,
                                S + OFF_DEG, S + OFF_DFLAT);
    fill_kernel<<<(E + 255) / 256, 256>>>(ei, E, curs, curd, lsrc, ldst);
    xwp_kernel<<<TOT / 8, dim3(32, 8)>>>(x, c1W, S + OFF_DEG, S + OFF_XWP);
    agg_gather_kernel<<<TOT * 32 / 256, 256>>>(odn, cdn, ldst, S + OFF_XWP,
                                               S + OFF_DEG, c1b, S + OFF_H);
    pool_softmax<<<TOT * 32 / 256, 256>>>(S + OFF_H, p1W, p1b, S + OFF_S1, TOT, KA, KAP);
    t1_gather_kernel<<<TOT * 32 / 256, 256>>>(osn, csn, lsrc, S + OFF_S1, S + OFF_T1);
    { dim3 g(2, BATCH); atb8_128_kernel<<<g, 256>>>(S + OFF_S1, S + OFF_T1, S + OFF_ADJR1, S + OFF_SS1); }
    atb8_32_kernel<<<BATCH, 256>>>(S + OFF_S1, S + OFF_H, S + OFF_X1);
    loss_norm_kernel<<<BATCH, 128>>>(S + OFF_ADJR1, S + OFF_SS1, S + OFF_S1, S + OFF_DFLAT,
                                     S + OFF_ADJ1, S + OFF_DFLAT2, S + OFF_LOSSB,
                                     KA, NNODE, KAP, KAP, KAP * KAP);
    stage2_conv_kernel<<<BATCH, 256, 62272>>>(S + OFF_ADJ1, S + OFF_X1, c2rW, c2rb, c2oW,
                                              p2W, p2b, S + OFF_X2, S + OFF_S2);
    stage2b_kernel<<<BATCH, 256, 60800>>>(S + OFF_ADJ1, S + OFF_S2, S + OFF_X2,
                                          S + OFF_ADJR2, S + OFF_SS2, S + OFF_X3);
    loss_norm_kernel<<<BATCH, 128>>>(S + OFF_ADJR2, S + OFF_SS2, S + OFF_S2, S + OFF_DFLAT2,
                                     S + OFF_ADJ2, S + OFF_DUMMY, S + OFF_LOSSB,
                                     KB, KA, KB, KB, KB * KB);
    tail_kernel<<<BATCH, 32>>>(S + OFF_ADJ2, S + OFF_X3, c3rW, c3rb, c3oW,
                               l1W, l1b, l2W, l2b, out);
    final_kernel<<<1, 128>>>(S + OFF_LOSSB, out, out_size);
}

// round 5
// speedup vs baseline: 2.6061x; 1.0833x over previous
#include <cuda_runtime.h>
#include <math.h>

namespace {
constexpr int BATCH = 128, NNODE = 512, INC = 128, HID = 32, KA = 100, KB = 10, OC = 10;
constexpr int KAP = 128;
constexpr int TOT = BATCH * NNODE;
constexpr int MAXE = BATCH * 8192;
constexpr float EPSV = 1e-15f;

constexpr size_t OFF_DEG    = 0;
constexpr size_t OFF_DFLAT  = OFF_DEG + TOT;
constexpr size_t OFF_LOSSB  = OFF_DFLAT + TOT;
constexpr size_t OFF_XWP    = OFF_LOSSB + BATCH;
constexpr size_t OFF_H      = OFF_XWP   + (size_t)TOT * HID;
constexpr size_t OFF_S1     = OFF_H     + (size_t)TOT * HID;
constexpr size_t OFF_T1     = OFF_S1    + (size_t)TOT * KAP;
constexpr size_t OFF_ADJR1  = OFF_T1    + (size_t)TOT * KAP;
constexpr size_t OFF_SS1    = OFF_ADJR1 + (size_t)BATCH * KAP * KAP;
constexpr size_t OFF_X1     = OFF_SS1   + (size_t)BATCH * KAP * KAP;
constexpr size_t OFF_ADJ1   = OFF_X1    + (size_t)BATCH * KA * HID;
constexpr size_t OFF_DFLAT2 = OFF_ADJ1  + (size_t)BATCH * KA * KA;
constexpr size_t OFF_DUMMY  = OFF_DFLAT2+ (size_t)BATCH * KA;
constexpr size_t OFF_X2     = OFF_DUMMY + (size_t)BATCH * KB;
constexpr size_t OFF_S2     = OFF_X2    + (size_t)BATCH * KA * HID;
constexpr size_t OFF_ADJR2  = OFF_S2    + (size_t)BATCH * KA * KB;
constexpr size_t OFF_SS2    = OFF_ADJR2 + (size_t)BATCH * KB * KB;
constexpr size_t OFF_X3     = OFF_SS2   + (size_t)BATCH * KB * KB;
constexpr size_t OFF_ADJ2   = OFF_X3    + (size_t)BATCH * KB * HID;
constexpr size_t SCRATCH_TOTAL = OFF_ADJ2 + (size_t)BATCH * KB * KB;
}  // namespace

__device__ __align__(16) float g_scratch[SCRATCH_TOTAL];
__device__ __align__(16) int g_cnt_src[TOT];
__device__ __align__(16) int g_cnt_dst[TOT];
__device__ __align__(16) int g_off_src[TOT];
__device__ __align__(16) int g_off_dst[TOT];
__device__ __align__(16) int g_cur_src[TOT];
__device__ __align__(16) int g_cur_dst[TOT];
__device__ __align__(16) int g_list_src[MAXE];
__device__ __align__(16) int g_list_dst[MAXE];

// ---------------------------------------------------------------------------
__global__ void zero_state_kernel(int* cs, int* cd, float* lossb) {
    int i = blockIdx.x * blockDim.x + threadIdx.x;
    if (i < TOT) { cs[i] = 0; cd[i] = 0; }
    if (i < BATCH) lossb[i] = 0.f;
}

__global__ void count_kernel(const int* __restrict__ ei, int E,
                             int* __restrict__ cs, int* __restrict__ cd) {
    int e = blockIdx.x * blockDim.x + threadIdx.x;
    if (e >= E) return;
    atomicAdd(&cs[ei[e]], 1);
    atomicAdd(&cd[ei[E + e]], 1);
}

__global__ __launch_bounds__(512) void scan_kernel(
    const int* __restrict__ cs, const int* __restrict__ cd, int eper,
    int* __restrict__ off_src, int* __restrict__ cur_src,
    int* __restrict__ off_dst, int* __restrict__ cur_dst,
    float* __restrict__ deg, float* __restrict__ dflat) {
    __shared__ int sh[512];
    int b = blockIdx.x, tid = threadIdx.x;
    int g = (b << 9) + tid;
    int base = b * eper;
    int vs = cs[g], vd = cd[g];
    dflat[g] = (float)vs;
    deg[g]   = (float)vd;
    sh[tid] = vs; __syncthreads();
    for (int o = 1; o < 512; o <<= 1) {
        int t = (tid >= o) ? sh[tid - o] : 0;
        __syncthreads(); sh[tid] += t; __syncthreads();
    }
    int es = sh[tid] - vs;
    off_src[g] = base + es; cur_src[g] = base + es;
    __syncthreads();
    sh[tid] = vd; __syncthreads();
    for (int o = 1; o < 512; o <<= 1) {
        int t = (tid >= o) ? sh[tid - o] : 0;
        __syncthreads(); sh[tid] += t; __syncthreads();
    }
    int ed = sh[tid] - vd;
    off_dst[g] = base + ed; cur_dst[g] = base + ed;
}

__global__ void fill_kernel(const int* __restrict__ ei, int E,
                            int* __restrict__ cur_src, int* __restrict__ cur_dst,
                            int* __restrict__ list_src, int* __restrict__ list_dst) {
    int e = blockIdx.x * blockDim.x + threadIdx.x;
    if (e >= E) return;
    int s = ei[e], d = ei[E + e];
    int p = atomicAdd(&cur_src[s], 1);
    list_src[p] = d & 511;
    int q = atomicAdd(&cur_dst[d], 1);
    list_dst[q] = s & 511;
}

// ---------------------------------------------------------------------------
__global__ __launch_bounds__(256) void xwp_kernel(const float* __restrict__ x,
                                                  const float* __restrict__ W,
                                                  const float* __restrict__ deg,
                                                  float* __restrict__ xwp) {
    __shared__ float Ws[INC * HID];
    __shared__ float xs[8][INC];
    int tid = threadIdx.y * 32 + threadIdx.x;
    for (int t = tid; t < INC * HID; t += 256) Ws[t] = W[t];
    int r0 = blockIdx.x * 8;
    for (int t = tid; t < 8 * INC; t += 256) {
        int r = t >> 7, k = t & 127;
        xs[r][k] = x[(size_t)(r0 + r) * INC + k];
    }
    __syncthreads();
    int c = threadIdx.x, r = threadIdx.y;
    float acc = 0.f;
#pragma unroll 8
    for (int k = 0; k < INC; k++) acc += xs[r][k] * Ws[k * HID + c];
    int g = r0 + r;
    float dis = rsqrtf(deg[g] + 1.0f);
    xwp[(size_t)g * HID + c] = dis * acc;
}

// ---------------------------------------------------------------------------
__global__ __launch_bounds__(256) void agg_gather_kernel(
    const int* __restrict__ off_dst, const int* __restrict__ cnt_dst,
    const int* __restrict__ list_dst,
    const float* __restrict__ xwp, const float* __restrict__ deg,
    const float* __restrict__ bias, float* __restrict__ h) {
    int node = (blockIdx.x * blockDim.x + threadIdx.x) >> 5;
    int lane = threadIdx.x & 31;
    if (node >= TOT) return;
    int b = node >> 9;
    const float* xb = xwp + (((size_t)b << 9) << 5);
    int off = off_dst[node], cnt = cnt_dst[node];
    float acc = 0.f;
    int i = off, end = off + cnt;
    for (; i + 3 < end; i += 4) {
        int s0 = __ldg(&list_dst[i]),   s1 = __ldg(&list_dst[i + 1]);
        int s2 = __ldg(&list_dst[i + 2]), s3 = __ldg(&list_dst[i + 3]);
        acc += xb[(s0 << 5) + lane] + xb[(s1 << 5) + lane]
             + xb[(s2 << 5) + lane] + xb[(s3 << 5) + lane];
    }
    for (; i < end; i++) acc += xb[(__ldg(&list_dst[i]) << 5) + lane];
    float dis = rsqrtf(deg[node] + 1.0f);
    float xv = xwp[((size_t)node << 5) + lane];
    h[((size_t)node << 5) + lane] = fmaxf(dis * (acc + xv) + bias[lane], 0.f);
}

// ---------------------------------------------------------------------------
__global__ __launch_bounds__(256) void t1_gather_kernel(
    const int* __restrict__ off_src, const int* __restrict__ cnt_src,
    const int* __restrict__ list_src,
    const float* __restrict__ s1p, float* __restrict__ T1) {
    int node = (blockIdx.x * blockDim.x + threadIdx.x) >> 5;
    int lane = threadIdx.x & 31;
    if (node >= TOT) return;
    int b = node >> 9;
    const float4* sb = (const float4*)(s1p + (((size_t)b << 9) << 7)) + lane;
    int off = off_src[node], cnt = cnt_src[node];
    float4 acc = make_float4(0, 0, 0, 0);
    int i = off, end = off + cnt;
    for (; i + 3 < end; i += 4) {
        int d0 = __ldg(&list_src[i]),     d1 = __ldg(&list_src[i + 1]);
        int d2 = __ldg(&list_src[i + 2]), d3 = __ldg(&list_src[i + 3]);
        float4 v0 = __ldg(&sb[d0 << 5]);
        float4 v1 = __ldg(&sb[d1 << 5]);
        float4 v2 = __ldg(&sb[d2 << 5]);
        float4 v3 = __ldg(&sb[d3 << 5]);
        acc.x += (v0.x + v1.x) + (v2.x + v3.x);
        acc.y += (v0.y + v1.y) + (v2.y + v3.y);
        acc.z += (v0.z + v1.z) + (v2.z + v3.z);
        acc.w += (v0.w + v1.w) + (v2.w + v3.w);
    }
    for (; i < end; i++) {
        float4 v = __ldg(&sb[__ldg(&list_src[i]) << 5]);
        acc.x += v.x; acc.y += v.y; acc.z += v.z; acc.w += v.w;
    }
    ((float4*)(T1 + ((size_t)node << 7)))[lane] = acc;
}

// ---------------------------------------------------------------------------
// adjr1 = s1^T T1 (sel=0) / ss1 = s1^T s1 (sel=1). Double-buffered smem,
// 128x128 tile, K=512, micro 8x8.
// ---------------------------------------------------------------------------
__global__ __launch_bounds__(256) void atb8_128_kernel(const float* __restrict__ s1p,
                                                       const float* __restrict__ T1,
                                                       float* __restrict__ adjr1,
                                                       float* __restrict__ ss1) {
    __shared__ float As[2][16][128];
    __shared__ float Bs[2][16][128];
    int b = blockIdx.y;
    int sel = blockIdx.x;
    const float* A = s1p + ((size_t)b << 9) * KAP;
    const float* B = (sel ? s1p : T1) + ((size_t)b << 9) * KAP;
    float* C = (sel ? ss1 : adjr1) + (size_t)b * KAP * KAP;
    int tid = threadIdx.x;
    int tx = tid & 15, ty = tid >> 4;
    // loader coords (2 float4 per array per tile)
    int lk0 = tid >> 5,        lj0 = (tid & 31) << 2;
    int lk1 = (tid + 256) >> 5, lj1 = ((tid + 256) & 31) << 2;

    float4 pa0, pa1, pb0, pb1;
    pa0 = *(const float4*)(A + lk0 * KAP + lj0);
    pa1 = *(const float4*)(A + lk1 * KAP + lj1);
    pb0 = *(const float4*)(B + lk0 * KAP + lj0);
    pb1 = *(const float4*)(B + lk1 * KAP + lj1);
    *(float4*)&As[0][lk0][lj0] = pa0;
    *(float4*)&As[0][lk1][lj1] = pa1;
    *(float4*)&Bs[0][lk0][lj0] = pb0;
    *(float4*)&Bs[0][lk1][lj1] = pb1;
    __syncthreads();

    float acc[8][8] = {};
    int cur = 0;
    for (int n0 = 0; n0 < NNODE; n0 += 16) {
        int nn = n0 + 16;
        if (nn < NNODE) {
            pa0 = *(const float4*)(A + (nn + lk0) * KAP + lj0);
            pa1 = *(const float4*)(A + (nn + lk1) * KAP + lj1);
            pb0 = *(const float4*)(B + (nn + lk0) * KAP + lj0);
            pb1 = *(const float4*)(B + (nn + lk1) * KAP + lj1);
        }
#pragma unroll
        for (int kk = 0; kk < 16; kk++) {
            float4 a0 = *(float4*)&As[cur][kk][ty * 8];
            float4 a1 = *(float4*)&As[cur][kk][ty * 8 + 4];
            float4 b0 = *(float4*)&Bs[cur][kk][tx * 8];
            float4 b1 = *(float4*)&Bs[cur][kk][tx * 8 + 4];
            float a[8] = {a0.x, a0.y, a0.z, a0.w, a1.x, a1.y, a1.z, a1.w};
            float bv[8] = {b0.x, b0.y, b0.z, b0.w, b1.x, b1.y, b1.z, b1.w};
#pragma unroll
            for (int u = 0; u < 8; u++)
#pragma unroll
                for (int v = 0; v < 8; v++) acc[u][v] += a[u] * bv[v];
        }
        if (nn < NNODE) {
            int nx = cur ^ 1;
            *(float4*)&As[nx][lk0][lj0] = pa0;
            *(float4*)&As[nx][lk1][lj1] = pa1;
            *(float4*)&Bs[nx][lk0][lj0] = pb0;
            *(float4*)&Bs[nx][lk1][lj1] = pb1;
            __syncthreads();
            cur = nx;
        }
    }
#pragma unroll
    for (int u = 0; u < 8; u++) {
        int row = ty * 8 + u;
        *(float4*)&C[(size_t)row * KAP + tx * 8] =
            make_float4(acc[u][0], acc[u][1], acc[u][2], acc[u][3]);
        *(float4*)&C[(size_t)row * KAP + tx * 8 + 4] =
            make_float4(acc[u][4], acc[u][5], acc[u][6], acc[u][7]);
    }
}

// ---------------------------------------------------------------------------
__global__ __launch_bounds__(256) void atb8_32_kernel(const float* __restrict__ s1p,
                                                      const float* __restrict__ h,
                                                      float* __restrict__ x1) {
    __shared__ float As[16][128];
    __shared__ float Bs[16][32];
    int b = blockIdx.x;
    const float* A = s1p + ((size_t)b << 9) * KAP;
    const float* B = h + ((size_t)b << 9) * HID;
    float* C = x1 + (size_t)b * KA * HID;
    int tid = threadIdx.x;
    int tx = tid & 7, ty = tid >> 3;
    float acc[4][4] = {};
    for (int n0 = 0; n0 < NNODE; n0 += 16) {
#pragma unroll
        for (int r = 0; r < 2; r++) {
            int t4 = tid + r * 256;
            int kk = t4 >> 5, jf = (t4 & 31) << 2;
            *(float4*)&As[kk][jf] = *(const float4*)(A + (n0 + kk) * KAP + jf);
        }
        if (tid < 128) {
            int kk = tid >> 3, jf = (tid & 7) << 2;
            *(float4*)&Bs[kk][jf] = *(const float4*)(B + (n0 + kk) * HID + jf);
        }
        __syncthreads();
#pragma unroll
        for (int kk = 0; kk < 16; kk++) {
            float4 av = *(float4*)&As[kk][ty * 4];
            float4 bb = *(float4*)&Bs[kk][tx * 4];
            float a[4] = {av.x, av.y, av.z, av.w};
            float bv[4] = {bb.x, bb.y, bb.z, bb.w};
#pragma unroll
            for (int u = 0; u < 4; u++)
#pragma unroll
                for (int v = 0; v < 4; v++) acc[u][v] += a[u] * bv[v];
        }
        __syncthreads();
    }
#pragma unroll
    for (int u = 0; u < 4; u++) {
        int row = ty * 4 + u;
        if (row < KA)
            *(float4*)&C[(size_t)row * HID + tx * 4] =
                make_float4(acc[u][0], acc[u][1], acc[u][2], acc[u][3]);
    }
}

// ---------------------------------------------------------------------------
// stage-1 pooled softmax: S[row][k] = softmax_k( h[row]@p1W + b ), k<100,
// output padded to 128 with zeros. W staged in smem [c][128]; __expf; no
// max-subtraction (shift-invariant, |z| small).
// ---------------------------------------------------------------------------
__global__ __launch_bounds__(256) void pool_softmax1_kernel(
    const float* __restrict__ X, const float* __restrict__ W,
    const float* __restrict__ bias, float* __restrict__ Sout) {
    __shared__ float Ws[HID * KAP];   // 16 KB, Ws[c*128 + k]
    __shared__ float bs[KAP];
    int tid = threadIdx.x;
    for (int t = tid; t < HID * KAP; t += 256) {
        int c = t >> 7, k = t & 127;
        Ws[t] = (k < KA) ? W[c * KA + k] : 0.f;
    }
    if (tid < KAP) bs[tid] = (tid < KA) ? bias[tid] : 0.f;
    __syncthreads();
    int lane = tid & 31, warp = tid >> 5;
    int row0 = blockIdx.x * 64 + warp * 8;
#pragma unroll
    for (int r = 0; r < 8; r++) {
        int row = row0 + r;
        float xv = X[(size_t)row * HID + lane];
        float a0 = bs[lane], a1 = bs[32 + lane], a2 = bs[64 + lane], a3 = bs[96 + lane];
#pragma unroll
        for (int c = 0; c < HID; c++) {
            float bx = __shfl_sync(0xffffffffu, xv, c);
            const float* wr = Ws + (c << 7) + lane;
            a0 += bx * wr[0];
            a1 += bx * wr[32];
            a2 += bx * wr[64];
            a3 += bx * wr[96];
        }
        float e0 = __expf(a0), e1 = __expf(a1), e2 = __expf(a2);
        float e3 = (96 + lane < KA) ? __expf(a3) : 0.f;
        float s = (e0 + e1) + (e2 + e3);
#pragma unroll
        for (int o = 16; o; o >>= 1) s += __shfl_xor_sync(0xffffffffu, s, o);
        float inv = __frcp_rn(s);
        float* op = Sout + (size_t)row * KAP + lane;
        op[0]  = e0 * inv;
        op[32] = e1 * inv;
        op[64] = e2 * inv;
        op[96] = e3 * inv;
    }
}

// ---------------------------------------------------------------------------
__device__ __forceinline__ float blockReduce128(float v, float* sm) {
    int t = threadIdx.x;
    sm[t] = v;
    __syncthreads();
    for (int s = 64; s > 0; s >>= 1) {
        if (t < s) sm[t] += sm[t + s];
        __syncthreads();
    }
    float r = sm[0];
    __syncthreads();
    return r;
}

__global__ void loss_norm_kernel(const float* __restrict__ raw,
                                 const float* __restrict__ ss,
                                 const float* __restrict__ s,
                                 const float* __restrict__ dflat,
                                 float* __restrict__ adjn,
                                 float* __restrict__ dflat2,
                                 float* __restrict__ lossb,
                                 int k, int n, int ld, int ld_s, int bstride) {
    int b = blockIdx.x;
    raw  += (size_t)b * bstride;
    ss   += (size_t)b * bstride;
    s    += (size_t)b * n * ld_s;
    dflat+= (size_t)b * n;
    adjn += (size_t)b * k * k;
    dflat2 += (size_t)b * k;
    __shared__ float sm[128];
    __shared__ float idc[128];
    int tid = threadIdx.x;

    float v = 0.f;
    for (int i = tid; i < k; i += 128) v += raw[i * ld + i];
    float num = blockReduce128(v, sm);

    v = 0.f;
    for (int nn = tid; nn < n; nn += 128) {
        float dv = dflat[nn];
        float acc = 0.f;
        for (int kk = 0; kk < k; kk++) {
            float sv = s[(size_t)nn * ld_s + kk];
            acc += sv * sv;
        }
        v += acc * dv;
    }
    float den = blockReduce128(v, sm);

    v = 0.f;
    for (int i = tid; i < k; i += 128)
        for (int j = 0; j < k; j++) { float t = ss[i * ld + j]; v += t * t; }
    float nrm = sqrtf(blockReduce128(v, sm));

    float invn = 1.0f / nrm;
    float dk = rsqrtf((float)k);
    v = 0.f;
    for (int i = tid; i < k; i += 128)
        for (int j = 0; j < k; j++) {
            float t = ss[i * ld + j] * invn - ((i == j) ? dk : 0.f);
            v += t * t;
        }
    float ortho = sqrtf(blockReduce128(v, sm));

    for (int i = tid; i < k; i += 128) {
        float r = 0.f;
        for (int j = 0; j < k; j++) if (j != i) r += raw[i * ld + j];
        idc[i] = 1.0f / (sqrtf(r) + EPSV);
    }
    __syncthreads();
    for (int idx = tid; idx < k * k; idx += 128) {
        int i = idx / k, j = idx - i * k;
        adjn[idx] = (i == j) ? 0.f : raw[i * ld + j] * idc[i] * idc[j];
    }
    for (int i = tid; i < k; i += 128) {
        float r = 0.f;
        for (int j = 0; j < k; j++) if (j != i) r += raw[i * ld + j] * idc[j];
        dflat2[i] = r * idc[i];
    }
    if (tid == 0) lossb[b] += -num / den + ortho;
}

// ---------------------------------------------------------------------------
__global__ __launch_bounds__(256) void stage2_conv_kernel(
    const float* __restrict__ adj1, const float* __restrict__ x1,
    const float* __restrict__ relW, const float* __restrict__ relb,
    const float* __restrict__ rootW,
    const float* __restrict__ p2W, const float* __restrict__ p2b,
    float* __restrict__ x2, float* __restrict__ s2) {
    extern __shared__ float sm[];
    float* adj1s = sm;
    float* x1s   = sm + 10000;
    float* relWs = sm + 13200;
    float* rootWs= sm + 14224;
    float* p2Ws  = sm + 15248;
    int b = blockIdx.x, tid = threadIdx.x;
    const float* A = adj1 + (size_t)b * KA * KA;
    const float* X = x1 + (size_t)b * KA * HID;
    for (int i = tid; i < KA * KA; i += 256) adj1s[i] = A[i];
    for (int i = tid; i < KA * HID; i += 256) x1s[i] = X[i];
    for (int i = tid; i < HID * HID; i += 256) { relWs[i] = relW[i]; rootWs[i] = rootW[i]; }
    for (int i = tid; i < HID * KB; i += 256) p2Ws[i] = p2W[i];
    __syncthreads();
    int lane = tid & 31, warp = tid >> 5;
    float rb = relb[lane];
    int kk10 = lane < KB ? lane : 0;
    float p2bv = p2b[kk10];
    for (int i = warp; i < KA; i += 8) {
        float t2 = 0.f;
        const float* ar = adj1s + i * KA;
        for (int m = 0; m < KA; m++) t2 += ar[m] * x1s[(m << 5) + lane];
        float x1v = x1s[(i << 5) + lane];
        float a = rb;
#pragma unroll
        for (int k = 0; k < 32; k++)
            a += __shfl_sync(0xffffffffu, t2, k) * relWs[(k << 5) + lane]
               + __shfl_sync(0xffffffffu, x1v, k) * rootWs[(k << 5) + lane];
        float x2v = fmaxf(a, 0.f);
        x2[((size_t)b * KA + i) * HID + lane] = x2v;
        float zz = p2bv;
#pragma unroll
        for (int c = 0; c < 32; c++)
            zz += __shfl_sync(0xffffffffu, x2v, c) * p2Ws[c * KB + kk10];
        float e = (lane < KB) ? __expf(zz) : 0.f;
        float ssum = e;
#pragma unroll
        for (int o = 16; o; o >>= 1) ssum += __shfl_xor_sync(0xffffffffu, ssum, o);
        if (lane < KB) s2[((size_t)b * KA + i) * KB + lane] = e / ssum;
    }
}

// ---------------------------------------------------------------------------
__global__ __launch_bounds__(256) void stage2b_kernel(
    const float* __restrict__ adj1, const float* __restrict__ s2,
    const float* __restrict__ x2,
    float* __restrict__ adjr2, float* __restrict__ ss2, float* __restrict__ x3) {
    extern __shared__ float sm[];
    float* adj1s = sm;
    float* s2s   = sm + 10000;
    float* x2s   = sm + 11000;
    float* tt2s  = sm + 14200;
    int b = blockIdx.x, tid = threadIdx.x;
    const float* A = adj1 + (size_t)b * KA * KA;
    const float* S2 = s2 + (size_t)b * KA * KB;
    const float* X2 = x2 + (size_t)b * KA * HID;
    for (int i = tid; i < KA * KA; i += 256) adj1s[i] = A[i];
    for (int i = tid; i < KA * KB; i += 256) s2s[i] = S2[i];
    for (int i = tid; i < KA * HID; i += 256) x2s[i] = X2[i];
    __syncthreads();
    for (int t = tid; t < KA * KB; t += 256) {
        int i = t / KB, k = t - i * KB;
        float a = 0.f;
        const float* ar = adj1s + i * KA;
        for (int m = 0; m < KA; m++) a += ar[m] * s2s[m * KB + k];
        tt2s[t] = a;
    }
    __syncthreads();
    for (int t = tid; t < 520; t += 256) {
        if (t < 100) {
            int i = t / 10, j = t - i * 10;
            float a = 0.f;
            for (int n = 0; n < KA; n++) a += s2s[n * KB + i] * tt2s[n * KB + j];
            adjr2[(size_t)b * 100 + t] = a;
        } else if (t < 200) {
            int u = t - 100;
            int i = u / 10, j = u - i * 10;
            float a = 0.f;
            for (int n = 0; n < KA; n++) a += s2s[n * KB + i] * s2s[n * KB + j];
            ss2[(size_t)b * 100 + u] = a;
        } else {
            int u = t - 200;
            int i = u >> 5, c = u & 31;
            float a = 0.f;
            for (int n = 0; n < KA; n++) a += s2s[n * KB + i] * x2s[(n << 5) + c];
            x3[(size_t)b * 320 + u] = a;
        }
    }
}

// ---------------------------------------------------------------------------
__global__ void tail_kernel(const float* __restrict__ adj2, const float* __restrict__ x3,
                            const float* __restrict__ c3rW, const float* __restrict__ c3rb,
                            const float* __restrict__ c3oW,
                            const float* __restrict__ l1W, const float* __restrict__ l1b,
                            const float* __restrict__ l2W, const float* __restrict__ l2b,
                            float* __restrict__ out) {
    int b = blockIdx.x, lane = threadIdx.x;
    const float* A2 = adj2 + (size_t)b * 100;
    const float* X3 = x3 + (size_t)b * 320;
    float x3c[10], t3c[10];
#pragma unroll
    for (int j = 0; j < 10; j++) x3c[j] = X3[j * 32 + lane];
#pragma unroll
    for (int i = 0; i < 10; i++) {
        float a = 0.f;
#pragma unroll
        for (int j = 0; j < 10; j++) a += A2[i * 10 + j] * x3c[j];
        t3c[i] = a;
    }
    float rb = c3rb[lane];
    float g = 0.f;
#pragma unroll
    for (int i = 0; i < 10; i++) {
        float a = rb;
#pragma unroll
        for (int k = 0; k < 32; k++)
            a += __shfl_sync(0xffffffffu, t3c[i], k) * c3rW[k * 32 + lane]
               + __shfl_sync(0xffffffffu, x3c[i], k) * c3oW[k * 32 + lane];
        g += a;
    }
    g *= 0.1f;
    float a1 = l1b[lane];
#pragma unroll
    for (int k = 0; k < 32; k++) a1 += __shfl_sync(0xffffffffu, g, k) * l1W[k * 32 + lane];
    float gg = fmaxf(a1, 0.f);
    int kk = lane < OC ? lane : 0;
    float a2 = l2b[kk];
#pragma unroll
    for (int k = 0; k < 32; k++) a2 += __shfl_sync(0xffffffffu, gg, k) * l2W[k * OC + kk];
    float val = (lane < OC) ? a2 : -INFINITY;
    float m = val;
#pragma unroll
    for (int o = 16; o; o >>= 1) m = fmaxf(m, __shfl_xor_sync(0xffffffffu, m, o));
    float e = (lane < OC) ? __expf(val - m) : 0.f;
    float ssum = e;
#pragma unroll
    for (int o = 16; o; o >>= 1) ssum += __shfl_xor_sync(0xffffffffu, ssum, o);
    if (lane < OC) out[b * OC + lane] = val - m - logf(ssum);
}

__global__ void final_kernel(const float* __restrict__ lossb, float* __restrict__ out,
                             int out_size) {
    __shared__ float sm[128];
    int t = threadIdx.x;
    sm[t] = lossb[t];
    __syncthreads();
    for (int s = 64; s > 0; s >>= 1) {
        if (t < s) sm[t] += sm[t + s];
        __syncthreads();
    }
    if (t == 0 && out_size > BATCH * OC) out[BATCH * OC] = sm[0] / (float)BATCH;
}

// ---------------------------------------------------------------------------
extern "C" void kernel_launch(void* const* d_in, const int* in_sizes, int n_in,
                              void* d_out, int out_size) {
    const float* x    = (const float*)d_in[0];
    const int*   ei   = (const int*)  d_in[1];
    const float* c1W  = (const float*)d_in[3];
    const float* c1b  = (const float*)d_in[4];
    const float* p1W  = (const float*)d_in[5];
    const float* p1b  = (const float*)d_in[6];
    const float* c2rW = (const float*)d_in[7];
    const float* c2rb = (const float*)d_in[8];
    const float* c2oW = (const float*)d_in[9];
    const float* p2W  = (const float*)d_in[10];
    const float* p2b  = (const float*)d_in[11];
    const float* c3rW = (const float*)d_in[12];
    const float* c3rb = (const float*)d_in[13];
    const float* c3oW = (const float*)d_in[14];
    const float* l1W  = (const float*)d_in[15];
    const float* l1b  = (const float*)d_in[16];
    const float* l2W  = (const float*)d_in[17];
    const float* l2b  = (const float*)d_in[18];
    float* out = (float*)d_out;
    int E = in_sizes[1] / 2;
    int eper = E / BATCH;

    void* sp = nullptr;
    cudaGetSymbolAddress(&sp, g_scratch);
    float* S = (float*)sp;
    int *csn, *cdn, *osn, *odn, *curs, *curd, *lsrc, *ldst;
    cudaGetSymbolAddress((void**)&csn, g_cnt_src);
    cudaGetSymbolAddress((void**)&cdn, g_cnt_dst);
    cudaGetSymbolAddress((void**)&osn, g_off_src);
    cudaGetSymbolAddress((void**)&odn, g_off_dst);
    cudaGetSymbolAddress((void**)&curs, g_cur_src);
    cudaGetSymbolAddress((void**)&curd, g_cur_dst);
    cudaGetSymbolAddress((void**)&lsrc, g_list_src);
    cudaGetSymbolAddress((void**)&ldst, g_list_dst);

    cudaFuncSetAttribute(stage2_conv_kernel, cudaFuncAttributeMaxDynamicSharedMemorySize, 62272);
    cudaFuncSetAttribute(stage2b_kernel, cudaFuncAttributeMaxDynamicSharedMemorySize, 60800);

    zero_state_kernel<<<(TOT + 255) / 256, 256>>>(csn, cdn, S + OFF_LOSSB);
    count_kernel<<<(E + 255) / 256, 256>>>(ei, E, csn, cdn);
    scan_kernel<<<BATCH, 512>>>(csn, cdn, eper, osn, curs, odn, curd,
                                S + OFF_DEG, S + OFF_DFLAT);
    fill_kernel<<<(E + 255) / 256, 256>>>(ei, E, curs, curd, lsrc, ldst);
    xwp_kernel<<<TOT / 8, dim3(32, 8)>>>(x, c1W, S + OFF_DEG, S + OFF_XWP);
    agg_gather_kernel<<<TOT * 32 / 256, 256>>>(odn, cdn, ldst, S + OFF_XWP,
                                               S + OFF_DEG, c1b, S + OFF_H);
    pool_softmax1_kernel<<<TOT / 64, 256>>>(S + OFF_H, p1W, p1b, S + OFF_S1);
    t1_gather_kernel<<<TOT * 32 / 256, 256>>>(osn, csn, lsrc, S + OFF_S1, S + OFF_T1);
    { dim3 g(2, BATCH); atb8_128_kernel<<<g, 256>>>(S + OFF_S1, S + OFF_T1, S + OFF_ADJR1, S + OFF_SS1); }
    atb8_32_kernel<<<BATCH, 256>>>(S + OFF_S1, S + OFF_H, S + OFF_X1);
    loss_norm_kernel<<<BATCH, 128>>>(S + OFF_ADJR1, S + OFF_SS1, S + OFF_S1, S + OFF_DFLAT,
                                     S + OFF_ADJ1, S + OFF_DFLAT2, S + OFF_LOSSB,
                                     KA, NNODE, KAP, KAP, KAP * KAP);
    stage2_conv_kernel<<<BATCH, 256, 62272>>>(S + OFF_ADJ1, S + OFF_X1, c2rW, c2rb, c2oW,
                                              p2W, p2b, S + OFF_X2, S + OFF_S2);
    stage2b_kernel<<<BATCH, 256, 60800>>>(S + OFF_ADJ1, S + OFF_S2, S + OFF_X2,
                                          S + OFF_ADJR2, S + OFF_SS2, S + OFF_X3);
    loss_norm_kernel<<<BATCH, 128>>>(S + OFF_ADJR2, S + OFF_SS2, S + OFF_S2, S + OFF_DFLAT2,
                                     S + OFF_ADJ2, S + OFF_DUMMY, S + OFF_LOSSB,
                                     KB, KA, KB, KB, KB * KB);
    tail_kernel<<<BATCH, 32>>>(S + OFF_ADJ2, S + OFF_X3, c3rW, c3rb, c3oW,
                               l1W, l1b, l2W, l2b, out);
    final_kernel<<<1, 128>>>(S + OFF_LOSSB, out, out_size);
}